// round 9
// baseline (speedup 1.0000x reference)
#include <cuda_runtime.h>
#include <cuda_bf16.h>
#include <math.h>

// ---------------- problem constants ----------------
#define BB 4
#define LL 512
#define VV 32000
#define DD 1024
#define HH 16
#define HD 64
#define NLAYER 2
#define EE 8
#define KK 2
#define FF 4096
#define SS (BB*LL)      // 2048
#define CAP 320
#define D3 (3*DD)       // 3072

typedef __nv_bfloat16 bf16;

// ---------------- static scratch ----------------
__device__ float g_x[SS*DD];
__device__ float g_qkv[SS*D3];
__device__ float g_vt[SS*DD];           // V transposed per head (f32, for old-path av GEMM)
__device__ float g_av[SS*DD];
__device__ float g_sc[BB*HH*LL*LL];     // 64 MB
__device__ float g_tmp[SS*DD];
__device__ float g_oe[EE*CAP*DD];
__device__ int   g_topi[SS*2];
__device__ float g_topw[SS*2];
__device__ int   g_slot[EE*CAP];
__device__ float g_slotw[EE*CAP];

// bf16 hi/lo activation buffers
__device__ bf16 g_xh[SS*DD];
__device__ bf16 g_xl[SS*DD];
__device__ bf16 g_qh[SS*DD];
__device__ bf16 g_ql[SS*DD];
__device__ bf16 g_kh[SS*DD];
__device__ bf16 g_kl[SS*DD];
__device__ bf16 g_attnh[SS*DD];
__device__ bf16 g_attnl[SS*DD];
__device__ bf16 g_xeh[EE*CAP*DD];
__device__ bf16 g_xel[EE*CAP*DD];
__device__ bf16 g_hh[EE*CAP*FF];
__device__ bf16 g_hl[EE*CAP*FF];

// bf16 hi/lo weight buffers (converted once per launch)
__device__ bf16 g_wih[NLAYER*D3*DD];
__device__ bf16 g_wil[NLAYER*D3*DD];
__device__ bf16 g_woh[NLAYER*DD*DD];
__device__ bf16 g_wol[NLAYER*DD*DD];
__device__ bf16 g_w1h[NLAYER*EE*FF*DD];
__device__ bf16 g_w1l[NLAYER*EE*FF*DD];
__device__ bf16 g_w2h[NLAYER*EE*DD*FF];
__device__ bf16 g_w2l[NLAYER*EE*DD*FF];
__device__ bf16 g_dwh[VV*DD];
__device__ bf16 g_dwl[VV*DD];

// ---------------- reductions ----------------
__device__ __forceinline__ float blockReduceSum(float v){
    __shared__ float sh[32];
    int lane = threadIdx.x & 31, wid = threadIdx.x >> 5;
    int nw = (blockDim.x + 31) >> 5;
    #pragma unroll
    for (int o = 16; o > 0; o >>= 1) v += __shfl_down_sync(0xffffffffu, v, o);
    __syncthreads();
    if (lane == 0) sh[wid] = v;
    __syncthreads();
    if (wid == 0) {
        v = (lane < nw) ? sh[lane] : 0.f;
        #pragma unroll
        for (int o = 16; o > 0; o >>= 1) v += __shfl_down_sync(0xffffffffu, v, o);
        if (lane == 0) sh[0] = v;
    }
    __syncthreads();
    return sh[0];
}

__device__ __forceinline__ float blockReduceMax(float v){
    __shared__ float sh[32];
    int lane = threadIdx.x & 31, wid = threadIdx.x >> 5;
    int nw = (blockDim.x + 31) >> 5;
    #pragma unroll
    for (int o = 16; o > 0; o >>= 1) v = fmaxf(v, __shfl_down_sync(0xffffffffu, v, o));
    __syncthreads();
    if (lane == 0) sh[wid] = v;
    __syncthreads();
    if (wid == 0) {
        v = (lane < nw) ? sh[lane] : -1e30f;
        #pragma unroll
        for (int o = 16; o > 0; o >>= 1) v = fmaxf(v, __shfl_down_sync(0xffffffffu, v, o));
        if (lane == 0) sh[0] = v;
    }
    __syncthreads();
    return sh[0];
}

// ---------------- common helpers ----------------
#define MMA_BF16(d, a, b) \
    asm volatile("mma.sync.aligned.m16n8k16.row.col.f32.bf16.bf16.f32 " \
        "{%0,%1,%2,%3},{%4,%5,%6,%7},{%8,%9},{%0,%1,%2,%3};" \
        : "+f"(d[0]), "+f"(d[1]), "+f"(d[2]), "+f"(d[3]) \
        : "r"(a[0]), "r"(a[1]), "r"(a[2]), "r"(a[3]), "r"(b[0]), "r"(b[1]))

#define LDSM4(r0, r1, r2, r3, addr) \
    asm volatile("ldmatrix.sync.aligned.m8n8.x4.shared.b16 {%0,%1,%2,%3}, [%4];" \
        : "=r"(r0), "=r"(r1), "=r"(r2), "=r"(r3) : "r"(addr))

__device__ __forceinline__ void splt2(float x, float y, unsigned& hi, unsigned& lo){
    __nv_bfloat162 H, L;
    H.x = __float2bfloat16_rn(x);
    H.y = __float2bfloat16_rn(y);
    L.x = __float2bfloat16_rn(x - __bfloat162float(H.x));
    L.y = __float2bfloat16_rn(y - __bfloat162float(H.y));
    hi = *(unsigned*)&H;
    lo = *(unsigned*)&L;
}

__device__ __forceinline__ void splt1(float v, bf16& h, bf16& l){
    h = __float2bfloat16_rn(v);
    l = __float2bfloat16_rn(v - __bfloat162float(h));
}

__device__ __forceinline__ void cp16(unsigned dst, const void* src, bool pred){
    asm volatile("cp.async.cg.shared.global [%0], [%1], 16, %2;"
        :: "r"(dst), "l"(src), "r"(pred ? 16 : 0));
}

// ============================================================
// NEW: pre-split bf16 GEMM (operands already hi/lo bf16):
//   C = act(alpha * (Ah+Al)(MxK) * (Bh+Bl)(NxK)^T + bias)
// Block 128x128x32, 8 warps, warp tile 64x32, m16n8k16.
// 2-stage cp.async pipeline, ONE barrier per K-iter.
// Mainloop/warp/iter: 8 cp.async + 12 LDSM + 48 MMA.
// ============================================================
#define GBM 128
#define GBN 128
#define GBK 32
#define LDW 20                          // tile row stride in words
#define TILE_W (GBM * LDW)              // words per tile (2560)
#define STAGE_W (4 * TILE_W)            // Ah,Al,Bh,Bl
#define BS_SMEM_BYTES (2 * STAGE_W * 4) // 81920

__global__ void __launch_bounds__(256, 2)
gemm_bs(const bf16* __restrict__ Ah, const bf16* __restrict__ Al,
        const bf16* __restrict__ Bh, const bf16* __restrict__ Bl,
        const float* __restrict__ bias, float* __restrict__ C,
        bf16* __restrict__ Ch, bf16* __restrict__ Cl,
        int M, int N, int K, int lda, int ldb, int ldc,
        long aStride, long bStride, long cStride, long biasStride,
        float alpha, int relu, int causal, int outSplit)
{
    extern __shared__ unsigned smw[];

    int m0 = blockIdx.x * GBM;
    int n0 = blockIdx.y * GBN;
    if (causal && n0 > m0 + GBM - 1) return;

    int z = blockIdx.z;
    Ah += (long)z * aStride;  Al += (long)z * aStride;
    Bh += (long)z * bStride;  Bl += (long)z * bStride;
    if (C)  C  += (long)z * cStride;
    if (Ch) { Ch += (long)z * cStride; Cl += (long)z * cStride; }
    if (bias) bias += (long)z * biasStride;

    int tid = threadIdx.x;
    int wid = tid >> 5, lane = tid & 31;
    int wm = (wid & 1) * 64;
    int wn = (wid >> 1) * 32;

    float c[4][4][4];
    #pragma unroll
    for (int i = 0; i < 4; i++)
        #pragma unroll
        for (int j = 0; j < 4; j++)
            #pragma unroll
            for (int r = 0; r < 4; r++) c[i][j][r] = 0.f;

    // cp.async mapping: thread -> one tile row + 32B (2 chunks)
    int cpRow = tid >> 1;            // 0..127
    int ch0   = (tid & 1) * 2;       // chunk pair: words ch0*4, k elems ch0*8
    int gmA = m0 + cpRow;  bool okA = gmA < M;  if (!okA) gmA = 0;
    int gnB = n0 + cpRow;  bool okB = gnB < N;  if (!okB) gnB = 0;

    unsigned smem_base = (unsigned)__cvta_generic_to_shared(smw);
    unsigned stageB[2] = { smem_base, smem_base + STAGE_W * 4 };
    unsigned dOff = (cpRow * LDW + ch0 * 4) * 4;

    auto issueCp = [&](int kt, int s) {
        unsigned aH = stageB[s];
        unsigned aL = aH + TILE_W * 4;
        unsigned bH = aL + TILE_W * 4;
        unsigned bL = bH + TILE_W * 4;
        const bf16* pAh = Ah + (long)gmA * lda + kt + ch0 * 8;
        const bf16* pAl = Al + (long)gmA * lda + kt + ch0 * 8;
        const bf16* pBh = Bh + (long)gnB * ldb + kt + ch0 * 8;
        const bf16* pBl = Bl + (long)gnB * ldb + kt + ch0 * 8;
        cp16(aH + dOff,      pAh,     okA);
        cp16(aH + dOff + 16, pAh + 8, okA);
        cp16(aL + dOff,      pAl,     okA);
        cp16(aL + dOff + 16, pAl + 8, okA);
        cp16(bH + dOff,      pBh,     okB);
        cp16(bH + dOff + 16, pBh + 8, okB);
        cp16(bL + dOff,      pBl,     okB);
        cp16(bL + dOff + 16, pBl + 8, okB);
        asm volatile("cp.async.commit_group;" ::: "memory");
    };

    // ldmatrix per-thread offsets (words)
    int aoff = (lane & 15) * LDW + ((lane >> 4) << 2);
    int boff = ((lane & 7) + ((lane >> 4) & 1) * 8) * LDW + ((lane >> 3) & 1) * 4;

    issueCp(0, 0);

    int nIter = K / GBK;
    for (int it = 0; it < nIter; it++) {
        __syncthreads();   // all warps done reading stage (it-1)&1 -> safe to overwrite
        bool more = (it + 1) < nIter;
        if (more) issueCp((it + 1) * GBK, (it + 1) & 1);
        if (more) asm volatile("cp.async.wait_group 1;" ::: "memory");
        else      asm volatile("cp.async.wait_group 0;" ::: "memory");
        // NOTE: per-thread wait; smem data this thread reads below was written by
        // its OWN cp? No — cross-thread. The __syncthreads above + wait ordering:
        // every thread issued the group for stage it&1 BEFORE the barrier of this
        // iter (prologue or previous iter), and wait_group here drains it chip-wide
        // per-thread; all threads wait on their own older group -> all writes to
        // stage it&1 complete before any thread proceeds? Each thread's wait only
        // guarantees its own copies. Need a barrier AFTER wait for cross-thread
        // visibility of the freshly waited stage on the FIRST touch:
        __syncthreads();

        unsigned sA_h = stageB[it & 1];
        unsigned sA_l = sA_h + TILE_W * 4;
        unsigned sB_h = sA_l + TILE_W * 4;
        unsigned sB_l = sB_h + TILE_W * 4;

        #pragma unroll
        for (int ks = 0; ks < 2; ks++) {
            int kw = ks * 8;
            unsigned ah[4][4], al[4][4], bh[4][2], bl[4][2];
            #pragma unroll
            for (int i = 0; i < 4; i++) {
                unsigned off = ((wm + i * 16) * LDW + aoff + kw) * 4;
                LDSM4(ah[i][0], ah[i][1], ah[i][2], ah[i][3], sA_h + off);
                LDSM4(al[i][0], al[i][1], al[i][2], al[i][3], sA_l + off);
            }
            #pragma unroll
            for (int p = 0; p < 2; p++) {
                unsigned off = ((wn + p * 16) * LDW + boff + kw) * 4;
                LDSM4(bh[p*2][0], bh[p*2][1], bh[p*2+1][0], bh[p*2+1][1], sB_h + off);
                LDSM4(bl[p*2][0], bl[p*2][1], bl[p*2+1][0], bl[p*2+1][1], sB_l + off);
            }
            #pragma unroll
            for (int i = 0; i < 4; i++)
                #pragma unroll
                for (int j = 0; j < 4; j++)
                    MMA_BF16(c[i][j], ah[i], bh[j]);
            #pragma unroll
            for (int i = 0; i < 4; i++)
                #pragma unroll
                for (int j = 0; j < 4; j++)
                    MMA_BF16(c[i][j], ah[i], bl[j]);
            #pragma unroll
            for (int i = 0; i < 4; i++)
                #pragma unroll
                for (int j = 0; j < 4; j++)
                    MMA_BF16(c[i][j], al[i], bh[j]);
        }
    }

    // ---- epilogue ----
    int cr = lane >> 2, cc = (lane & 3) * 2;
    #pragma unroll
    for (int i = 0; i < 4; i++) {
        #pragma unroll
        for (int j = 0; j < 4; j++) {
            int gn = n0 + wn + j * 8 + cc;
            #pragma unroll
            for (int half = 0; half < 2; half++) {
                int gm = m0 + wm + i * 16 + cr + half * 8;
                if (gm >= M) continue;
                float v0 = c[i][j][half * 2 + 0] * alpha;
                float v1 = c[i][j][half * 2 + 1] * alpha;
                if (bias) {
                    if (gn < N)     v0 += bias[gn];
                    if (gn + 1 < N) v1 += bias[gn + 1];
                }
                if (relu) { v0 = fmaxf(v0, 0.f); v1 = fmaxf(v1, 0.f); }
                if (outSplit) {
                    if (gn + 1 < N) {
                        unsigned h, l;
                        splt2(v0, v1, h, l);
                        *(unsigned*)(Ch + (long)gm * ldc + gn) = h;
                        *(unsigned*)(Cl + (long)gm * ldc + gn) = l;
                    }
                } else {
                    if (gn + 1 < N) {
                        *(float2*)(C + (long)gm * ldc + gn) = make_float2(v0, v1);
                    } else if (gn < N) {
                        C[(long)gm * ldc + gn] = v0;
                    }
                }
            }
        }
    }
}

// ============================================================
// OLD: f32-input GEMM with in-kernel split (kept for av GEMM)
// ============================================================
#define SFL 36
#define STAGE_F (2 * GBM * SFL)
#define SMEM_F32 (2 * STAGE_F)
#define SMEM_BF16 (4 * GBM * LDW)
#define GEMM_SMEM_BYTES ((SMEM_F32 + SMEM_BF16) * 4)   // 114688 B

__global__ void __launch_bounds__(256, 2)
gemm_tc(const float* __restrict__ A, const float* __restrict__ Bm,
        const float* __restrict__ bias, float* __restrict__ C,
        int M, int N, int K, int lda, int ldb, int ldc,
        long aStride, long bStride, long cStride, long biasStride,
        float alpha, int relu, int causal)
{
    extern __shared__ float smf[];
    unsigned* sAh = (unsigned*)(smf + SMEM_F32);
    unsigned* sAl = sAh + GBM * LDW;
    unsigned* sBh = sAl + GBM * LDW;
    unsigned* sBl = sBh + GBM * LDW;

    int m0 = blockIdx.x * GBM;
    int n0 = blockIdx.y * GBN;
    if (causal && n0 > m0 + GBM - 1) return;

    int z = blockIdx.z;
    A  += (long)z * aStride;
    Bm += (long)z * bStride;
    C  += (long)z * cStride;
    if (bias) bias += (long)z * biasStride;

    int tid = threadIdx.x;
    int wid = tid >> 5, lane = tid & 31;
    int wm = (wid & 1) * 64;
    int wn = (wid >> 1) * 32;

    float c[4][4][4];
    #pragma unroll
    for (int i = 0; i < 4; i++)
        #pragma unroll
        for (int j = 0; j < 4; j++)
            #pragma unroll
            for (int r = 0; r < 4; r++) c[i][j][r] = 0.f;

    int lrow = tid >> 3;
    int lcol = (tid & 7) * 4;
    int kp0  = (tid & 7) * 2;

    int gmRow[4], gnRow[4];
    bool gmOk[4], gnOk[4];
    #pragma unroll
    for (int r = 0; r < 4; r++) {
        int row = lrow + r * 32;
        int gm = m0 + row;
        gmOk[r] = gm < M; gmRow[r] = gmOk[r] ? gm : 0;
        int gn = n0 + row;
        gnOk[r] = gn < N; gnRow[r] = gnOk[r] ? gn : 0;
    }

    unsigned smem_base = (unsigned)__cvta_generic_to_shared(smf);
    unsigned stBase[2] = { smem_base, smem_base + STAGE_F * 4 };
    unsigned sAh_s = smem_base + SMEM_F32 * 4;
    unsigned sAl_s = sAh_s + GBM * LDW * 4;
    unsigned sBh_s = sAl_s + GBM * LDW * 4;
    unsigned sBl_s = sBh_s + GBM * LDW * 4;

    int aoff = (lane & 15) * LDW + ((lane >> 4) << 2);
    int boff = ((lane & 7) + ((lane >> 4) & 1) * 8) * LDW + ((lane >> 3) & 1) * 4;

    auto issueCp = [&](int kt, int s) {
        unsigned aBase = stBase[s];
        unsigned bBase = stBase[s] + GBM * SFL * 4;
        #pragma unroll
        for (int r = 0; r < 4; r++) {
            int row = lrow + r * 32;
            cp16(aBase + (row * SFL + lcol) * 4, A + (long)gmRow[r] * lda + kt + lcol, gmOk[r]);
            cp16(bBase + (row * SFL + lcol) * 4, Bm + (long)gnRow[r] * ldb + kt + lcol, gnOk[r]);
        }
        asm volatile("cp.async.commit_group;" ::: "memory");
    };

    issueCp(0, 0);

    int nIter = K / GBK;
    for (int it = 0; it < nIter; it++) {
        bool more = (it + 1) < nIter;
        if (more) issueCp((it + 1) * GBK, (it + 1) & 1);

        if (more) asm volatile("cp.async.wait_group 1;" ::: "memory");
        else      asm volatile("cp.async.wait_group 0;" ::: "memory");
        __syncthreads();

        {
            const float* stA = smf + (it & 1) * STAGE_F;
            const float* stB = stA + GBM * SFL;
            #pragma unroll
            for (int r = 0; r < 4; r++) {
                int row = lrow + r * 32;
                float4 va = *(const float4*)(stA + row * SFL + lcol);
                unsigned h0, l0, h1, l1;
                splt2(va.x, va.y, h0, l0);
                splt2(va.z, va.w, h1, l1);
                sAh[row * LDW + kp0]     = h0;
                sAh[row * LDW + kp0 + 1] = h1;
                sAl[row * LDW + kp0]     = l0;
                sAl[row * LDW + kp0 + 1] = l1;

                float4 vb = *(const float4*)(stB + row * SFL + lcol);
                splt2(vb.x, vb.y, h0, l0);
                splt2(vb.z, vb.w, h1, l1);
                sBh[row * LDW + kp0]     = h0;
                sBh[row * LDW + kp0 + 1] = h1;
                sBl[row * LDW + kp0]     = l0;
                sBl[row * LDW + kp0 + 1] = l1;
            }
        }
        __syncthreads();

        #pragma unroll
        for (int ks = 0; ks < 2; ks++) {
            int kw = ks * 8;
            unsigned ah[4][4], al[4][4], bh[4][2], bl[4][2];
            #pragma unroll
            for (int i = 0; i < 4; i++) {
                unsigned off = ((wm + i * 16) * LDW + aoff + kw) * 4;
                LDSM4(ah[i][0], ah[i][1], ah[i][2], ah[i][3], sAh_s + off);
                LDSM4(al[i][0], al[i][1], al[i][2], al[i][3], sAl_s + off);
            }
            #pragma unroll
            for (int p = 0; p < 2; p++) {
                unsigned off = ((wn + p * 16) * LDW + boff + kw) * 4;
                LDSM4(bh[p*2][0], bh[p*2][1], bh[p*2+1][0], bh[p*2+1][1], sBh_s + off);
                LDSM4(bl[p*2][0], bl[p*2][1], bl[p*2+1][0], bl[p*2+1][1], sBl_s + off);
            }
            #pragma unroll
            for (int i = 0; i < 4; i++)
                #pragma unroll
                for (int j = 0; j < 4; j++)
                    MMA_BF16(c[i][j], ah[i], bh[j]);
            #pragma unroll
            for (int i = 0; i < 4; i++)
                #pragma unroll
                for (int j = 0; j < 4; j++)
                    MMA_BF16(c[i][j], ah[i], bl[j]);
            #pragma unroll
            for (int i = 0; i < 4; i++)
                #pragma unroll
                for (int j = 0; j < 4; j++)
                    MMA_BF16(c[i][j], al[i], bh[j]);
        }
    }

    int cr = lane >> 2, cc = (lane & 3) * 2;
    #pragma unroll
    for (int i = 0; i < 4; i++) {
        #pragma unroll
        for (int j = 0; j < 4; j++) {
            int gn = n0 + wn + j * 8 + cc;
            #pragma unroll
            for (int half = 0; half < 2; half++) {
                int gm = m0 + wm + i * 16 + cr + half * 8;
                if (gm >= M) continue;
                float v0 = c[i][j][half * 2 + 0] * alpha;
                float v1 = c[i][j][half * 2 + 1] * alpha;
                if (bias) {
                    if (gn < N)     v0 += bias[gn];
                    if (gn + 1 < N) v1 += bias[gn + 1];
                }
                if (relu) { v0 = fmaxf(v0, 0.f); v1 = fmaxf(v1, 0.f); }
                if (gn + 1 < N) {
                    *(float2*)(C + (long)gm * ldc + gn) = make_float2(v0, v1);
                } else if (gn < N) {
                    C[(long)gm * ldc + gn] = v0;
                }
            }
        }
    }
}

// ---------------- weight f32 -> bf16 hi/lo convert ----------------
__global__ void convert_split(const float* __restrict__ src,
                              unsigned* __restrict__ hiw, unsigned* __restrict__ low,
                              long n4)
{
    long i = (long)blockIdx.x * 256 + threadIdx.x;
    if (i >= n4) return;
    float4 v = ((const float4*)src)[i];
    unsigned h0, l0, h1, l1;
    splt2(v.x, v.y, h0, l0);
    splt2(v.z, v.w, h1, l1);
    ((uint2*)hiw)[i] = make_uint2(h0, h1);
    ((uint2*)low)[i] = make_uint2(l0, l1);
}

// ---------------- embedding + positional encoding ----------------
__global__ void embed_kernel(const int* __restrict__ src, const float* __restrict__ emb,
                             float* __restrict__ x, bf16* __restrict__ xh, bf16* __restrict__ xl)
{
    long i = (long)blockIdx.x * 256 + threadIdx.x;
    int s = (int)(i >> 10);
    int d = (int)(i & 1023);
    int l = s & (LL - 1);
    int tok = src[s];
    int half2 = (d >> 1) * 2;
    float div = __expf(-(float)half2 * (logf(10000.f) / (float)DD));
    float arg = (float)l * div;
    float pe = (d & 1) ? cosf(arg) : sinf(arg);
    float v = emb[(long)tok * DD + d] * 32.0f + pe;
    x[i] = v;
    splt1(v, xh[i], xl[i]);
}

// ---------------- head split / merge ----------------
__global__ void split_heads(const float* __restrict__ qkv,
                            bf16* __restrict__ qh, bf16* __restrict__ ql,
                            bf16* __restrict__ kh, bf16* __restrict__ kl,
                            float* __restrict__ vt)
{
    long i = (long)blockIdx.x * 256 + threadIdx.x;
    int s = (int)(i >> 10);
    int dc = (int)(i & 1023);
    int h = dc >> 6;
    int d = dc & 63;
    int b = s >> 9;
    int l = s & 511;
    long srcoff = (long)s * D3 + h * HD + d;
    long dst = (((long)(b * HH + h) * LL) + l) * HD + d;
    splt1(qkv[srcoff],      qh[dst], ql[dst]);
    splt1(qkv[srcoff + DD], kh[dst], kl[dst]);
    long vdst = (((long)(b * HH + h) * HD) + d) * LL + l;
    vt[vdst] = qkv[srcoff + 2 * DD];
}

__global__ void merge_heads(const float* __restrict__ av,
                            bf16* __restrict__ oh, bf16* __restrict__ ol)
{
    long i = (long)blockIdx.x * 256 + threadIdx.x;
    int s = (int)(i >> 10);
    int dc = (int)(i & 1023);
    int h = dc >> 6;
    int d = dc & 63;
    int b = s >> 9;
    int l = s & 511;
    long srcoff = (((long)(b * HH + h) * LL) + l) * HD + d;
    splt1(av[srcoff], oh[i], ol[i]);
}

// ---------------- causal softmax (in place, f32) ----------------
__global__ void softmax_causal(float* __restrict__ sc)
{
    int row = blockIdx.x;
    int q = row & (LL - 1);
    float* s = sc + (long)row * LL;
    int t = threadIdx.x;

    float mx = -1e30f;
    for (int k = t; k <= q; k += 128) mx = fmaxf(mx, s[k]);
    mx = blockReduceMax(mx);

    float sum = 0.f;
    for (int k = t; k <= q; k += 128) {
        float e = expf(s[k] - mx);
        s[k] = e;
        sum += e;
    }
    sum = blockReduceSum(sum);
    float inv = 1.f / sum;
    for (int k = t; k <= q; k += 128) s[k] *= inv;
    for (int k = q + 1 + t; k < LL; k += 128) s[k] = 0.f;
}

// ---------------- residual + layernorm (f32 + bf16 hi/lo out) ----------------
__global__ void add_ln(const float* __restrict__ a, const float* __restrict__ b,
                       const float* __restrict__ w, const float* __restrict__ bb,
                       float* __restrict__ out, bf16* __restrict__ oh, bf16* __restrict__ ol)
{
    int row = blockIdx.x;
    int t = threadIdx.x;
    const float* pa = a + (long)row * DD;
    const float* pb = b + (long)row * DD;
    float v[4];
    float s = 0.f;
    #pragma unroll
    for (int i = 0; i < 4; i++) {
        int d = t + i * 256;
        v[i] = pa[d] + pb[d];
        s += v[i];
    }
    s = blockReduceSum(s);
    float mean = s * (1.f / DD);
    float qq = 0.f;
    #pragma unroll
    for (int i = 0; i < 4; i++) {
        float dd = v[i] - mean;
        qq += dd * dd;
    }
    qq = blockReduceSum(qq);
    float inv = rsqrtf(qq * (1.f / DD) + 1e-5f);
    #pragma unroll
    for (int i = 0; i < 4; i++) {
        int d = t + i * 256;
        float o = (v[i] - mean) * inv * w[d] + bb[d];
        long idx = (long)row * DD + d;
        out[idx] = o;
        splt1(o, oh[idx], ol[idx]);
    }
}

// ---------------- MoE gating ----------------
__global__ void gate_topk(const float* __restrict__ x, const float* __restrict__ gw,
                          const float* __restrict__ gb,
                          int* __restrict__ topi, float* __restrict__ topw)
{
    __shared__ float sh[EE * 256];
    int s = blockIdx.x, t = threadIdx.x;
    float p[EE];
    #pragma unroll
    for (int e = 0; e < EE; e++) p[e] = 0.f;
    for (int d = t; d < DD; d += 256) {
        float xv = x[(long)s * DD + d];
        #pragma unroll
        for (int e = 0; e < EE; e++) p[e] += xv * gw[e * DD + d];
    }
    #pragma unroll
    for (int e = 0; e < EE; e++) sh[e * 256 + t] = p[e];
    __syncthreads();
    for (int o = 128; o > 0; o >>= 1) {
        if (t < o) {
            #pragma unroll
            for (int e = 0; e < EE; e++) sh[e * 256 + t] += sh[e * 256 + t + o];
        }
        __syncthreads();
    }
    if (t == 0) {
        float lg[EE];
        float mx = -1e30f;
        #pragma unroll
        for (int e = 0; e < EE; e++) { lg[e] = sh[e * 256] + gb[e]; mx = fmaxf(mx, lg[e]); }
        float sum = 0.f;
        #pragma unroll
        for (int e = 0; e < EE; e++) { lg[e] = expf(lg[e] - mx); sum += lg[e]; }
        float invs = 1.f / sum;
        #pragma unroll
        for (int e = 0; e < EE; e++) lg[e] *= invs;
        int i0 = 0;
        #pragma unroll
        for (int e = 1; e < EE; e++) if (lg[e] > lg[i0]) i0 = e;
        int i1 = (i0 == 0) ? 1 : 0;
        #pragma unroll
        for (int e = 0; e < EE; e++) if (e != i0 && lg[e] > lg[i1]) i1 = e;
        float w0 = lg[i0], w1 = lg[i1];
        float ws = 1.f / (w0 + w1);
        topi[2 * s]     = i0;
        topi[2 * s + 1] = i1;
        topw[2 * s]     = w0 * ws;
        topw[2 * s + 1] = w1 * ws;
    }
}

// ---------------- capacity routing ----------------
__global__ void route_kernel(const int* __restrict__ topi, const float* __restrict__ topw,
                             int* __restrict__ slot, float* __restrict__ slotw)
{
    __shared__ int cnt[256];
    int e = blockIdx.x;
    int t = threadIdx.x;
    int base = t * 8;
    int loc[8]; float lw[8]; int c = 0;
    #pragma unroll
    for (int i = 0; i < 8; i++) {
        int s = base + i;
        float w = -1.f;
        if (topi[2 * s] == e) w = topw[2 * s];
        else if (topi[2 * s + 1] == e) w = topw[2 * s + 1];
        if (w >= 0.f) { loc[c] = s; lw[c] = w; c++; }
    }
    cnt[t] = c;
    __syncthreads();
    for (int off = 1; off < 256; off <<= 1) {
        int v = 0;
        if (t >= off) v = cnt[t - off];
        __syncthreads();
        cnt[t] += v;
        __syncthreads();
    }
    int start = cnt[t] - c;
    for (int i = 0; i < c; i++) {
        int pos = start + i;
        if (pos < CAP) {
            slot[e * CAP + pos]  = loc[i];
            slotw[e * CAP + pos] = lw[i];
        }
    }
    int total = cnt[255];
    __syncthreads();
    for (int p = total + t; p < CAP; p += 256) {
        slot[e * CAP + p]  = -1;
        slotw[e * CAP + p] = 0.f;
    }
}

__global__ void gather_xe(const bf16* __restrict__ xh, const bf16* __restrict__ xl,
                          const int* __restrict__ slot,
                          bf16* __restrict__ xeh, bf16* __restrict__ xel)
{
    int sl = blockIdx.x;
    int t = slot[sl];
    unsigned* dh = (unsigned*)(xeh + (long)sl * DD);
    unsigned* dl = (unsigned*)(xel + (long)sl * DD);
    if (t < 0) {
        for (int d = threadIdx.x; d < DD / 2; d += 256) { dh[d] = 0u; dl[d] = 0u; }
    } else {
        const unsigned* sh = (const unsigned*)(xh + (long)t * DD);
        const unsigned* sl2 = (const unsigned*)(xl + (long)t * DD);
        for (int d = threadIdx.x; d < DD / 2; d += 256) { dh[d] = sh[d]; dl[d] = sl2[d]; }
    }
}

__global__ void scatter_oe(const float* __restrict__ oe, const int* __restrict__ slot,
                           const float* __restrict__ slotw, float* __restrict__ y)
{
    int sl = blockIdx.x;
    int t = slot[sl];
    if (t < 0) return;
    float w = slotw[sl];
    const float* srcp = oe + (long)sl * DD;
    float* dst = y + (long)t * DD;
    for (int d = threadIdx.x; d < DD; d += 256) atomicAdd(&dst[d], srcp[d] * w);
}

// ---------------- host launcher ----------------
extern "C" void kernel_launch(void* const* d_in, const int* in_sizes, int n_in,
                              void* d_out, int out_size)
{
    const int*   src        = (const int*)  d_in[0];
    const float* emb        = (const float*)d_in[1];
    const float* in_proj_w  = (const float*)d_in[2];
    const float* in_proj_b  = (const float*)d_in[3];
    const float* out_proj_w = (const float*)d_in[4];
    const float* out_proj_b = (const float*)d_in[5];
    const float* ln1_w      = (const float*)d_in[6];
    const float* ln1_b      = (const float*)d_in[7];
    const float* ln2_w      = (const float*)d_in[8];
    const float* ln2_b      = (const float*)d_in[9];
    const float* gate_w     = (const float*)d_in[10];
    const float* gate_b     = (const float*)d_in[11];
    const float* w1         = (const float*)d_in[12];
    const float* b1         = (const float*)d_in[13];
    const float* w2         = (const float*)d_in[14];
    const float* b2         = (const float*)d_in[15];
    const float* dec_w      = (const float*)d_in[16];
    const float* dec_b      = (const float*)d_in[17];
    float* out = (float*)d_out;

    static int smem_set = 0;
    if (!smem_set) {
        cudaFuncSetAttribute(gemm_tc, cudaFuncAttributeMaxDynamicSharedMemorySize, GEMM_SMEM_BYTES);
        cudaFuncSetAttribute(gemm_bs, cudaFuncAttributeMaxDynamicSharedMemorySize, BS_SMEM_BYTES);
        smem_set = 1;
    }

    float *x, *qkv, *vt, *av, *sc, *tmp, *oe, *topw, *slotw;
    int *topi, *slot;
    bf16 *xh, *xl, *qh, *ql, *kh, *kl, *attnh, *attnl, *xeh, *xel, *hh, *hl;
    bf16 *wih, *wil, *woh, *wol, *w1h, *w1l, *w2h, *w2l, *dwh, *dwl;

    cudaGetSymbolAddress((void**)&x,    g_x);
    cudaGetSymbolAddress((void**)&qkv,  g_qkv);
    cudaGetSymbolAddress((void**)&vt,   g_vt);
    cudaGetSymbolAddress((void**)&av,   g_av);
    cudaGetSymbolAddress((void**)&sc,   g_sc);
    cudaGetSymbolAddress((void**)&tmp,  g_tmp);
    cudaGetSymbolAddress((void**)&oe,   g_oe);
    cudaGetSymbolAddress((void**)&topi, g_topi);
    cudaGetSymbolAddress((void**)&topw, g_topw);
    cudaGetSymbolAddress((void**)&slot, g_slot);
    cudaGetSymbolAddress((void**)&slotw, g_slotw);
    cudaGetSymbolAddress((void**)&xh, g_xh);
    cudaGetSymbolAddress((void**)&xl, g_xl);
    cudaGetSymbolAddress((void**)&qh, g_qh);
    cudaGetSymbolAddress((void**)&ql, g_ql);
    cudaGetSymbolAddress((void**)&kh, g_kh);
    cudaGetSymbolAddress((void**)&kl, g_kl);
    cudaGetSymbolAddress((void**)&attnh, g_attnh);
    cudaGetSymbolAddress((void**)&attnl, g_attnl);
    cudaGetSymbolAddress((void**)&xeh, g_xeh);
    cudaGetSymbolAddress((void**)&xel, g_xel);
    cudaGetSymbolAddress((void**)&hh, g_hh);
    cudaGetSymbolAddress((void**)&hl, g_hl);
    cudaGetSymbolAddress((void**)&wih, g_wih);
    cudaGetSymbolAddress((void**)&wil, g_wil);
    cudaGetSymbolAddress((void**)&woh, g_woh);
    cudaGetSymbolAddress((void**)&wol, g_wol);
    cudaGetSymbolAddress((void**)&w1h, g_w1h);
    cudaGetSymbolAddress((void**)&w1l, g_w1l);
    cudaGetSymbolAddress((void**)&w2h, g_w2h);
    cudaGetSymbolAddress((void**)&w2l, g_w2l);
    cudaGetSymbolAddress((void**)&dwh, g_dwh);
    cudaGetSymbolAddress((void**)&dwl, g_dwl);

    // ---- weight conversions (once per launch) ----
    auto conv = [&](const float* s, bf16* h, bf16* l, long n) {
        long n4 = n / 4;
        convert_split<<<(unsigned)((n4 + 255) / 256), 256>>>(s, (unsigned*)h, (unsigned*)l, n4);
    };
    conv(in_proj_w,  wih, wil, (long)NLAYER * D3 * DD);
    conv(out_proj_w, woh, wol, (long)NLAYER * DD * DD);
    conv(w1,         w1h, w1l, (long)NLAYER * EE * FF * DD);
    conv(w2,         w2h, w2l, (long)NLAYER * EE * DD * FF);
    conv(dec_w,      dwh, dwl, (long)VV * DD);

    embed_kernel<<<(SS * DD) / 256, 256>>>(src, emb, x, xh, xl);

    for (int l = 0; l < NLAYER; l++) {
        const float* bi  = in_proj_b  + (long)l * D3;
        const float* bo  = out_proj_b + (long)l * DD;
        const float* gw  = gate_w     + (long)l * EE * DD;
        const float* gb  = gate_b     + (long)l * EE;
        const float* b1l = b1         + (long)l * EE * FF;
        const float* b2l = b2         + (long)l * EE * DD;
        const bf16* wihl = wih + (long)l * D3 * DD;
        const bf16* will = wil + (long)l * D3 * DD;
        const bf16* wohl = woh + (long)l * DD * DD;
        const bf16* woll = wol + (long)l * DD * DD;
        const bf16* w1hl = w1h + (long)l * EE * FF * DD;
        const bf16* w1ll = w1l + (long)l * EE * FF * DD;
        const bf16* w2hl = w2h + (long)l * EE * DD * FF;
        const bf16* w2ll = w2l + (long)l * EE * DD * FF;

        // qkv = x @ wi^T + bi   [2048 x 3072], K=1024
        gemm_bs<<<dim3(SS/GBM, D3/GBN, 1), 256, BS_SMEM_BYTES>>>(
            xh, xl, wihl, will, bi, qkv, nullptr, nullptr,
            SS, D3, DD, DD, DD, D3, 0, 0, 0, 0, 1.f, 0, 0, 0);

        split_heads<<<(SS * DD) / 256, 256>>>(qkv, qh, ql, kh, kl, vt);

        // scores = q @ k^T / 8   batch=64, causal block skip
        gemm_bs<<<dim3(LL/GBM, LL/GBN, BB*HH), 256, BS_SMEM_BYTES>>>(
            qh, ql, kh, kl, nullptr, sc, nullptr, nullptr,
            LL, LL, HD, HD, HD, LL,
            (long)LL*HD, (long)LL*HD, (long)LL*LL, 0, 0.125f, 0, 1, 0);

        softmax_causal<<<BB * HH * LL, 128>>>(sc);

        // av = probs @ vt^T  (old f32-split path; probs stay f32)
        gemm_tc<<<dim3(LL/GBM, 1, BB*HH), 256, GEMM_SMEM_BYTES>>>(sc, vt, nullptr, av,
            LL, HD, LL, LL, LL, HD,
            (long)LL*LL, (long)HD*LL, (long)LL*HD, 0, 1.f, 0, 0);

        merge_heads<<<(SS * DD) / 256, 256>>>(av, attnh, attnl);

        // proj = attn @ wo^T + bo
        gemm_bs<<<dim3(SS/GBM, DD/GBN, 1), 256, BS_SMEM_BYTES>>>(
            attnh, attnl, wohl, woll, bo, tmp, nullptr, nullptr,
            SS, DD, DD, DD, DD, DD, 0, 0, 0, 0, 1.f, 0, 0, 0);

        add_ln<<<SS, 256>>>(x, tmp, ln1_w + l * DD, ln1_b + l * DD, x, xh, xl);

        // ---- MoE ----
        gate_topk<<<SS, 256>>>(x, gw, gb, topi, topw);
        route_kernel<<<EE, 256>>>(topi, topw, slot, slotw);
        gather_xe<<<EE * CAP, 256>>>(xh, xl, slot, xeh, xel);

        // h = relu(xe @ w1^T + b1) -> bf16 hi/lo output
        gemm_bs<<<dim3((CAP+GBM-1)/GBM, FF/GBN, EE), 256, BS_SMEM_BYTES>>>(
            xeh, xel, w1hl, w1ll, b1l, nullptr, hh, hl,
            CAP, FF, DD, DD, DD, FF,
            (long)CAP*DD, (long)FF*DD, (long)CAP*FF, FF, 1.f, 1, 0, 1);

        // oe = h @ w2^T + b2
        gemm_bs<<<dim3((CAP+GBM-1)/GBM, DD/GBN, EE), 256, BS_SMEM_BYTES>>>(
            hh, hl, w2hl, w2ll, b2l, oe, nullptr, nullptr,
            CAP, DD, FF, FF, FF, DD,
            (long)CAP*FF, (long)DD*FF, (long)CAP*DD, DD, 1.f, 0, 0, 0);

        cudaMemsetAsync(tmp, 0, (size_t)SS * DD * sizeof(float), 0);
        scatter_oe<<<EE * CAP, 256>>>(oe, slot, slotw, tmp);

        add_ln<<<SS, 256>>>(x, tmp, ln2_w + l * DD, ln2_b + l * DD, x, xh, xl);
    }

    // logits = x @ dec_w^T + dec_b   [2048 x 32000], K=1024
    gemm_bs<<<dim3(SS/GBM, VV/GBN, 1), 256, BS_SMEM_BYTES>>>(
        xh, xl, dwh, dwl, dec_b, out, nullptr, nullptr,
        SS, VV, DD, DD, DD, VV, 0, 0, 0, 0, 1.f, 0, 0, 0);
}

// round 11
// speedup vs baseline: 1.4959x; 1.4959x over previous
#include <cuda_runtime.h>
#include <cuda_bf16.h>
#include <cuda_fp16.h>
#include <math.h>

// ---------------- problem constants ----------------
#define BB 4
#define LL 512
#define VV 32000
#define DD 1024
#define HH 16
#define HD 64
#define NLAYER 2
#define EE 8
#define KK 2
#define FF 4096
#define SS (BB*LL)      // 2048
#define CAP 320
#define D3 (3*DD)       // 3072

// ---------------- static scratch ----------------
__device__ float g_x[SS*DD];
__device__ float g_qkv[SS*D3];
__device__ float g_q[SS*DD];
__device__ float g_k[SS*DD];
__device__ float g_vt[SS*DD];           // V transposed per head: [(b,h), d, l]
__device__ float g_av[SS*DD];
__device__ float g_sc[BB*HH*LL*LL];     // 64 MB
__device__ float g_attn[SS*DD];
__device__ float g_tmp[SS*DD];
__device__ float g_xe[EE*CAP*DD];
__device__ float g_hbuf[EE*CAP*FF];
__device__ float g_oe[EE*CAP*DD];
__device__ int   g_topi[SS*2];
__device__ float g_topw[SS*2];
__device__ int   g_slot[EE*CAP];
__device__ float g_slotw[EE*CAP];

// ---------------- reductions ----------------
__device__ __forceinline__ float blockReduceSum(float v){
    __shared__ float sh[32];
    int lane = threadIdx.x & 31, wid = threadIdx.x >> 5;
    int nw = (blockDim.x + 31) >> 5;
    #pragma unroll
    for (int o = 16; o > 0; o >>= 1) v += __shfl_down_sync(0xffffffffu, v, o);
    __syncthreads();
    if (lane == 0) sh[wid] = v;
    __syncthreads();
    if (wid == 0) {
        v = (lane < nw) ? sh[lane] : 0.f;
        #pragma unroll
        for (int o = 16; o > 0; o >>= 1) v += __shfl_down_sync(0xffffffffu, v, o);
        if (lane == 0) sh[0] = v;
    }
    __syncthreads();
    return sh[0];
}

__device__ __forceinline__ float blockReduceMax(float v){
    __shared__ float sh[32];
    int lane = threadIdx.x & 31, wid = threadIdx.x >> 5;
    int nw = (blockDim.x + 31) >> 5;
    #pragma unroll
    for (int o = 16; o > 0; o >>= 1) v = fmaxf(v, __shfl_down_sync(0xffffffffu, v, o));
    __syncthreads();
    if (lane == 0) sh[wid] = v;
    __syncthreads();
    if (wid == 0) {
        v = (lane < nw) ? sh[lane] : -1e30f;
        #pragma unroll
        for (int o = 16; o > 0; o >>= 1) v = fmaxf(v, __shfl_down_sync(0xffffffffu, v, o));
        if (lane == 0) sh[0] = v;
    }
    __syncthreads();
    return sh[0];
}

// ============================================================
// Tensor-core GEMM, fp16 2-pass split, cp.async + ldmatrix:
//   C = act(alpha * A(MxK) * B(NxK)^T + bias)
// A single-rounded fp16; B split into fp16 (hi, lo).
// D = Ah*Bh + Ah*Bl  (dropped (A-Ah)*B term ~2^-12 rel).
// Block 128x128x32, 8 warps, warp tile 64x32, m16n8k16.
// Per ks-chunk: 8 LDSM.x4 + 32 MMA  (was 12 + 48 with bf16x3).
// ============================================================
#define GBM 128
#define GBN 128
#define GBK 32
#define LDW 20    // fp16 buf row stride in 32-bit words (16 pairs + 4 pad)
#define SFL 36    // f32 stage row stride in floats (32 + 4 pad)
#define STAGE_F (2 * GBM * SFL)                 // floats per stage (A+B)
#define SMEM_F32 (2 * STAGE_F)                  // 72KB
#define SMEM_H16 (3 * GBM * LDW)                // Ah,Bh,Bl = 30KB
#define GEMM_SMEM_BYTES ((SMEM_F32 + SMEM_H16) * 4)   // 104448 B

#define MMA_F16(d, a, b) \
    asm volatile("mma.sync.aligned.m16n8k16.row.col.f32.f16.f16.f32 " \
        "{%0,%1,%2,%3},{%4,%5,%6,%7},{%8,%9},{%0,%1,%2,%3};" \
        : "+f"(d[0]), "+f"(d[1]), "+f"(d[2]), "+f"(d[3]) \
        : "r"(a[0]), "r"(a[1]), "r"(a[2]), "r"(a[3]), "r"(b[0]), "r"(b[1]))

#define LDSM4(r0, r1, r2, r3, addr) \
    asm volatile("ldmatrix.sync.aligned.m8n8.x4.shared.b16 {%0,%1,%2,%3}, [%4];" \
        : "=r"(r0), "=r"(r1), "=r"(r2), "=r"(r3) : "r"(addr))

__device__ __forceinline__ unsigned h2pack(float x, float y){
    __half2 H;
    H.x = __float2half_rn(x);
    H.y = __float2half_rn(y);
    return *(unsigned*)&H;
}

__device__ __forceinline__ void h2splt(float x, float y, unsigned& hi, unsigned& lo){
    __half2 H, L;
    H.x = __float2half_rn(x);
    H.y = __float2half_rn(y);
    L.x = __float2half_rn(x - __half2float(H.x));
    L.y = __float2half_rn(y - __half2float(H.y));
    hi = *(unsigned*)&H;
    lo = *(unsigned*)&L;
}

__device__ __forceinline__ void cp16(unsigned dst, const float* src, bool pred){
    asm volatile("cp.async.cg.shared.global [%0], [%1], 16, %2;"
        :: "r"(dst), "l"(src), "r"(pred ? 16 : 0));
}

__global__ void __launch_bounds__(256, 2)
gemm_tc(const float* __restrict__ A, const float* __restrict__ Bm,
        const float* __restrict__ bias, float* __restrict__ C,
        int M, int N, int K, int lda, int ldb, int ldc,
        long aStride, long bStride, long cStride, long biasStride,
        float alpha, int relu, int causal, int kcap)
{
    extern __shared__ float smf[];
    unsigned* sAh = (unsigned*)(smf + SMEM_F32);
    unsigned* sBh = sAh + GBM * LDW;
    unsigned* sBl = sBh + GBM * LDW;

    int m0 = blockIdx.x * GBM;
    int n0 = blockIdx.y * GBN;
    if (causal && n0 > m0 + GBM - 1) return;   // fully-masked causal block
    if (kcap) { int ke = m0 + GBM; if (ke < K) K = ke; }  // causal-prob A: cols >= m0+GBM are zero

    int z = blockIdx.z;
    A  += (long)z * aStride;
    Bm += (long)z * bStride;
    C  += (long)z * cStride;
    if (bias) bias += (long)z * biasStride;

    int tid = threadIdx.x;
    int wid = tid >> 5, lane = tid & 31;
    int wm = (wid & 1) * 64;
    int wn = (wid >> 1) * 32;

    float c[4][4][4];
    #pragma unroll
    for (int i = 0; i < 4; i++)
        #pragma unroll
        for (int j = 0; j < 4; j++)
            #pragma unroll
            for (int r = 0; r < 4; r++) c[i][j][r] = 0.f;

    int lrow = tid >> 3;           // 0..31
    int lcol = (tid & 7) * 4;      // gmem/stage k offset: 0,4,...,28
    int kp0  = (tid & 7) * 2;      // fp16-pair index: 0,2,...,14

    int gmRow[4], gnRow[4];
    bool gmOk[4], gnOk[4];
    #pragma unroll
    for (int r = 0; r < 4; r++) {
        int row = lrow + r * 32;
        int gm = m0 + row;
        gmOk[r] = gm < M; gmRow[r] = gmOk[r] ? gm : 0;
        int gn = n0 + row;
        gnOk[r] = gn < N; gnRow[r] = gnOk[r] ? gn : 0;
    }

    unsigned smem_base = (unsigned)__cvta_generic_to_shared(smf);
    unsigned stBase[2] = { smem_base, smem_base + STAGE_F * 4 };
    unsigned sAh_s = smem_base + SMEM_F32 * 4;
    unsigned sBh_s = sAh_s + GBM * LDW * 4;
    unsigned sBl_s = sBh_s + GBM * LDW * 4;

    // ldmatrix per-thread offsets (words)
    int aoff = (lane & 15) * LDW + ((lane >> 4) << 2);
    int boff = ((lane & 7) + ((lane >> 4) & 1) * 8) * LDW + ((lane >> 3) & 1) * 4;

    auto issueCp = [&](int kt, int s) {
        unsigned aBase = stBase[s];
        unsigned bBase = stBase[s] + GBM * SFL * 4;
        #pragma unroll
        for (int r = 0; r < 4; r++) {
            int row = lrow + r * 32;
            cp16(aBase + (row * SFL + lcol) * 4, A + (long)gmRow[r] * lda + kt + lcol, gmOk[r]);
            cp16(bBase + (row * SFL + lcol) * 4, Bm + (long)gnRow[r] * ldb + kt + lcol, gnOk[r]);
        }
        asm volatile("cp.async.commit_group;" ::: "memory");
    };

    issueCp(0, 0);

    int nIter = K / GBK;
    for (int it = 0; it < nIter; it++) {
        bool more = (it + 1) < nIter;
        if (more) issueCp((it + 1) * GBK, (it + 1) & 1);

        if (more) asm volatile("cp.async.wait_group 1;" ::: "memory");
        else      asm volatile("cp.async.wait_group 0;" ::: "memory");
        __syncthreads();

        // ---- convert f32 stage -> fp16 buffers (A hi only; B hi+lo) ----
        {
            const float* stA = smf + (it & 1) * STAGE_F;
            const float* stB = stA + GBM * SFL;
            #pragma unroll
            for (int r = 0; r < 4; r++) {
                int row = lrow + r * 32;
                float4 va = *(const float4*)(stA + row * SFL + lcol);
                sAh[row * LDW + kp0]     = h2pack(va.x, va.y);
                sAh[row * LDW + kp0 + 1] = h2pack(va.z, va.w);

                float4 vb = *(const float4*)(stB + row * SFL + lcol);
                unsigned h0, l0, h1, l1;
                h2splt(vb.x, vb.y, h0, l0);
                h2splt(vb.z, vb.w, h1, l1);
                sBh[row * LDW + kp0]     = h0;
                sBh[row * LDW + kp0 + 1] = h1;
                sBl[row * LDW + kp0]     = l0;
                sBl[row * LDW + kp0 + 1] = l1;
            }
        }
        __syncthreads();

        // ---- two k16 chunks, fragments via ldmatrix ----
        #pragma unroll
        for (int ks = 0; ks < 2; ks++) {
            int kw = ks * 8;   // word offset of this k16 chunk
            unsigned ah[4][4], bh[4][2], bl[4][2];
            #pragma unroll
            for (int i = 0; i < 4; i++) {
                unsigned off = ((wm + i * 16) * LDW + aoff + kw) * 4;
                LDSM4(ah[i][0], ah[i][1], ah[i][2], ah[i][3], sAh_s + off);
            }
            #pragma unroll
            for (int p = 0; p < 2; p++) {
                unsigned off = ((wn + p * 16) * LDW + boff + kw) * 4;
                LDSM4(bh[p*2][0], bh[p*2][1], bh[p*2+1][0], bh[p*2+1][1], sBh_s + off);
                LDSM4(bl[p*2][0], bl[p*2][1], bl[p*2+1][0], bl[p*2+1][1], sBl_s + off);
            }
            #pragma unroll
            for (int i = 0; i < 4; i++)
                #pragma unroll
                for (int j = 0; j < 4; j++)
                    MMA_F16(c[i][j], ah[i], bh[j]);
            #pragma unroll
            for (int i = 0; i < 4; i++)
                #pragma unroll
                for (int j = 0; j < 4; j++)
                    MMA_F16(c[i][j], ah[i], bl[j]);
        }
    }

    // ---- epilogue ----
    int cr = lane >> 2, cc = (lane & 3) * 2;
    #pragma unroll
    for (int i = 0; i < 4; i++) {
        #pragma unroll
        for (int j = 0; j < 4; j++) {
            int gn = n0 + wn + j * 8 + cc;
            #pragma unroll
            for (int half = 0; half < 2; half++) {
                int gm = m0 + wm + i * 16 + cr + half * 8;
                if (gm >= M) continue;
                float v0 = c[i][j][half * 2 + 0] * alpha;
                float v1 = c[i][j][half * 2 + 1] * alpha;
                if (bias) {
                    if (gn < N)     v0 += bias[gn];
                    if (gn + 1 < N) v1 += bias[gn + 1];
                }
                if (relu) { v0 = fmaxf(v0, 0.f); v1 = fmaxf(v1, 0.f); }
                if (gn + 1 < N) {
                    *(float2*)(C + (long)gm * ldc + gn) = make_float2(v0, v1);
                } else if (gn < N) {
                    C[(long)gm * ldc + gn] = v0;
                }
            }
        }
    }
}

// ---------------- embedding + positional encoding ----------------
__global__ void embed_kernel(const int* __restrict__ src, const float* __restrict__ emb,
                             float* __restrict__ x)
{
    long i = (long)blockIdx.x * 256 + threadIdx.x;
    int s = (int)(i >> 10);
    int d = (int)(i & 1023);
    int l = s & (LL - 1);
    int tok = src[s];
    int half2i = (d >> 1) * 2;
    float div = __expf(-(float)half2i * (logf(10000.f) / (float)DD));
    float arg = (float)l * div;
    float pe = (d & 1) ? cosf(arg) : sinf(arg);
    x[i] = emb[(long)tok * DD + d] * 32.0f + pe;
}

// ---------------- head split (V transposed) / merge ----------------
__global__ void split_heads(const float* __restrict__ qkv,
                            float* __restrict__ q, float* __restrict__ k, float* __restrict__ vt)
{
    long i = (long)blockIdx.x * 256 + threadIdx.x;
    int s = (int)(i >> 10);
    int dc = (int)(i & 1023);
    int h = dc >> 6;
    int d = dc & 63;
    int b = s >> 9;
    int l = s & 511;
    long srcoff = (long)s * D3 + h * HD + d;
    long dst = (((long)(b * HH + h) * LL) + l) * HD + d;
    q[dst] = qkv[srcoff];
    k[dst] = qkv[srcoff + DD];
    long vdst = (((long)(b * HH + h) * HD) + d) * LL + l;
    vt[vdst] = qkv[srcoff + 2 * DD];
}

__global__ void merge_heads(const float* __restrict__ av, float* __restrict__ out)
{
    long i = (long)blockIdx.x * 256 + threadIdx.x;
    int s = (int)(i >> 10);
    int dc = (int)(i & 1023);
    int h = dc >> 6;
    int d = dc & 63;
    int b = s >> 9;
    int l = s & 511;
    long srcoff = (((long)(b * HH + h) * LL) + l) * HD + d;
    out[i] = av[srcoff];
}

// ---------------- causal softmax (in place) ----------------
__global__ void softmax_causal(float* __restrict__ sc)
{
    int row = blockIdx.x;
    int q = row & (LL - 1);
    float* s = sc + (long)row * LL;
    int t = threadIdx.x;

    float mx = -1e30f;
    for (int k = t; k <= q; k += 128) mx = fmaxf(mx, s[k]);
    mx = blockReduceMax(mx);

    float sum = 0.f;
    for (int k = t; k <= q; k += 128) {
        float e = expf(s[k] - mx);
        s[k] = e;
        sum += e;
    }
    sum = blockReduceSum(sum);
    float inv = 1.f / sum;
    for (int k = t; k <= q; k += 128) s[k] *= inv;
    for (int k = q + 1 + t; k < LL; k += 128) s[k] = 0.f;
}

// ---------------- residual + layernorm ----------------
__global__ void add_ln(const float* __restrict__ a, const float* __restrict__ b,
                       const float* __restrict__ w, const float* __restrict__ bb,
                       float* __restrict__ out)
{
    int row = blockIdx.x;
    int t = threadIdx.x;
    const float* pa = a + (long)row * DD;
    const float* pb = b + (long)row * DD;
    float v[4];
    float s = 0.f;
    #pragma unroll
    for (int i = 0; i < 4; i++) {
        int d = t + i * 256;
        v[i] = pa[d] + pb[d];
        s += v[i];
    }
    s = blockReduceSum(s);
    float mean = s * (1.f / DD);
    float qq = 0.f;
    #pragma unroll
    for (int i = 0; i < 4; i++) {
        float dd = v[i] - mean;
        qq += dd * dd;
    }
    qq = blockReduceSum(qq);
    float inv = rsqrtf(qq * (1.f / DD) + 1e-5f);
    #pragma unroll
    for (int i = 0; i < 4; i++) {
        int d = t + i * 256;
        out[(long)row * DD + d] = (v[i] - mean) * inv * w[d] + bb[d];
    }
}

// ---------------- MoE gating ----------------
__global__ void gate_topk(const float* __restrict__ x, const float* __restrict__ gw,
                          const float* __restrict__ gb,
                          int* __restrict__ topi, float* __restrict__ topw)
{
    __shared__ float sh[EE * 256];
    int s = blockIdx.x, t = threadIdx.x;
    float p[EE];
    #pragma unroll
    for (int e = 0; e < EE; e++) p[e] = 0.f;
    for (int d = t; d < DD; d += 256) {
        float xv = x[(long)s * DD + d];
        #pragma unroll
        for (int e = 0; e < EE; e++) p[e] += xv * gw[e * DD + d];
    }
    #pragma unroll
    for (int e = 0; e < EE; e++) sh[e * 256 + t] = p[e];
    __syncthreads();
    for (int o = 128; o > 0; o >>= 1) {
        if (t < o) {
            #pragma unroll
            for (int e = 0; e < EE; e++) sh[e * 256 + t] += sh[e * 256 + t + o];
        }
        __syncthreads();
    }
    if (t == 0) {
        float lg[EE];
        float mx = -1e30f;
        #pragma unroll
        for (int e = 0; e < EE; e++) { lg[e] = sh[e * 256] + gb[e]; mx = fmaxf(mx, lg[e]); }
        float sum = 0.f;
        #pragma unroll
        for (int e = 0; e < EE; e++) { lg[e] = expf(lg[e] - mx); sum += lg[e]; }
        float invs = 1.f / sum;
        #pragma unroll
        for (int e = 0; e < EE; e++) lg[e] *= invs;
        int i0 = 0;
        #pragma unroll
        for (int e = 1; e < EE; e++) if (lg[e] > lg[i0]) i0 = e;
        int i1 = (i0 == 0) ? 1 : 0;
        #pragma unroll
        for (int e = 0; e < EE; e++) if (e != i0 && lg[e] > lg[i1]) i1 = e;
        float w0 = lg[i0], w1 = lg[i1];
        float ws = 1.f / (w0 + w1);
        topi[2 * s]     = i0;
        topi[2 * s + 1] = i1;
        topw[2 * s]     = w0 * ws;
        topw[2 * s + 1] = w1 * ws;
    }
}

// ---------------- capacity routing: parallel block scan per expert ----------------
__global__ void route_kernel(const int* __restrict__ topi, const float* __restrict__ topw,
                             int* __restrict__ slot, float* __restrict__ slotw)
{
    __shared__ int cnt[256];
    int e = blockIdx.x;
    int t = threadIdx.x;
    int base = t * 8;
    int loc[8]; float lw[8]; int c = 0;
    #pragma unroll
    for (int i = 0; i < 8; i++) {
        int s = base + i;
        float w = -1.f;
        if (topi[2 * s] == e) w = topw[2 * s];
        else if (topi[2 * s + 1] == e) w = topw[2 * s + 1];
        if (w >= 0.f) { loc[c] = s; lw[c] = w; c++; }
    }
    cnt[t] = c;
    __syncthreads();
    for (int off = 1; off < 256; off <<= 1) {
        int v = 0;
        if (t >= off) v = cnt[t - off];
        __syncthreads();
        cnt[t] += v;
        __syncthreads();
    }
    int start = cnt[t] - c;
    for (int i = 0; i < c; i++) {
        int pos = start + i;
        if (pos < CAP) {
            slot[e * CAP + pos]  = loc[i];
            slotw[e * CAP + pos] = lw[i];
        }
    }
    int total = cnt[255];
    __syncthreads();
    for (int p = total + t; p < CAP; p += 256) {
        slot[e * CAP + p]  = -1;
        slotw[e * CAP + p] = 0.f;
    }
}

__global__ void gather_xe(const float* __restrict__ x, const int* __restrict__ slot,
                          float* __restrict__ xe)
{
    int sl = blockIdx.x;
    int t = slot[sl];
    float* dst = xe + (long)sl * DD;
    if (t < 0) {
        for (int d = threadIdx.x; d < DD; d += 256) dst[d] = 0.f;
    } else {
        const float* srcp = x + (long)t * DD;
        for (int d = threadIdx.x; d < DD; d += 256) dst[d] = srcp[d];
    }
}

__global__ void scatter_oe(const float* __restrict__ oe, const int* __restrict__ slot,
                           const float* __restrict__ slotw, float* __restrict__ y)
{
    int sl = blockIdx.x;
    int t = slot[sl];
    if (t < 0) return;
    float w = slotw[sl];
    const float* srcp = oe + (long)sl * DD;
    float* dst = y + (long)t * DD;
    for (int d = threadIdx.x; d < DD; d += 256) atomicAdd(&dst[d], srcp[d] * w);
}

// ---------------- host launcher ----------------
extern "C" void kernel_launch(void* const* d_in, const int* in_sizes, int n_in,
                              void* d_out, int out_size)
{
    const int*   src        = (const int*)  d_in[0];
    const float* emb        = (const float*)d_in[1];
    const float* in_proj_w  = (const float*)d_in[2];
    const float* in_proj_b  = (const float*)d_in[3];
    const float* out_proj_w = (const float*)d_in[4];
    const float* out_proj_b = (const float*)d_in[5];
    const float* ln1_w      = (const float*)d_in[6];
    const float* ln1_b      = (const float*)d_in[7];
    const float* ln2_w      = (const float*)d_in[8];
    const float* ln2_b      = (const float*)d_in[9];
    const float* gate_w     = (const float*)d_in[10];
    const float* gate_b     = (const float*)d_in[11];
    const float* w1         = (const float*)d_in[12];
    const float* b1         = (const float*)d_in[13];
    const float* w2         = (const float*)d_in[14];
    const float* b2         = (const float*)d_in[15];
    const float* dec_w      = (const float*)d_in[16];
    const float* dec_b      = (const float*)d_in[17];
    float* out = (float*)d_out;

    static int smem_set = 0;
    if (!smem_set) {
        cudaFuncSetAttribute(gemm_tc, cudaFuncAttributeMaxDynamicSharedMemorySize, GEMM_SMEM_BYTES);
        smem_set = 1;
    }

    float *x, *qkv, *q, *k, *vt, *av, *sc, *attn, *tmp, *xe, *hbuf, *oe, *topw, *slotw;
    int *topi, *slot;
    cudaGetSymbolAddress((void**)&x,    g_x);
    cudaGetSymbolAddress((void**)&qkv,  g_qkv);
    cudaGetSymbolAddress((void**)&q,    g_q);
    cudaGetSymbolAddress((void**)&k,    g_k);
    cudaGetSymbolAddress((void**)&vt,   g_vt);
    cudaGetSymbolAddress((void**)&av,   g_av);
    cudaGetSymbolAddress((void**)&sc,   g_sc);
    cudaGetSymbolAddress((void**)&attn, g_attn);
    cudaGetSymbolAddress((void**)&tmp,  g_tmp);
    cudaGetSymbolAddress((void**)&xe,   g_xe);
    cudaGetSymbolAddress((void**)&hbuf, g_hbuf);
    cudaGetSymbolAddress((void**)&oe,   g_oe);
    cudaGetSymbolAddress((void**)&topi, g_topi);
    cudaGetSymbolAddress((void**)&topw, g_topw);
    cudaGetSymbolAddress((void**)&slot, g_slot);
    cudaGetSymbolAddress((void**)&slotw, g_slotw);

    embed_kernel<<<(SS * DD) / 256, 256>>>(src, emb, x);

    for (int l = 0; l < NLAYER; l++) {
        const float* wi = in_proj_w  + (long)l * D3 * DD;
        const float* bi = in_proj_b  + (long)l * D3;
        const float* wo = out_proj_w + (long)l * DD * DD;
        const float* bo = out_proj_b + (long)l * DD;
        const float* gw = gate_w     + (long)l * EE * DD;
        const float* gb = gate_b     + (long)l * EE;
        const float* w1l = w1        + (long)l * EE * FF * DD;
        const float* b1l = b1        + (long)l * EE * FF;
        const float* w2l = w2        + (long)l * EE * DD * FF;
        const float* b2l = b2        + (long)l * EE * DD;

        // qkv = x @ wi^T + bi   [2048 x 3072], K=1024
        gemm_tc<<<dim3(SS/GBM, D3/GBN, 1), 256, GEMM_SMEM_BYTES>>>(x, wi, bi, qkv,
            SS, D3, DD, DD, DD, D3, 0, 0, 0, 0, 1.f, 0, 0, 0);

        split_heads<<<(SS * DD) / 256, 256>>>(qkv, q, k, vt);

        // scores = q @ k^T / 8   batch=64, M=N=512, K=64, causal block skip
        gemm_tc<<<dim3(LL/GBM, LL/GBN, BB*HH), 256, GEMM_SMEM_BYTES>>>(q, k, nullptr, sc,
            LL, LL, HD, HD, HD, LL,
            (long)LL*HD, (long)LL*HD, (long)LL*LL, 0, 0.125f, 0, 1, 0);

        softmax_causal<<<BB * HH * LL, 128>>>(sc);

        // av = probs @ vt^T   batch=64, M=512, N=64, K=512; probs zero past diag -> kcap
        gemm_tc<<<dim3(LL/GBM, 1, BB*HH), 256, GEMM_SMEM_BYTES>>>(sc, vt, nullptr, av,
            LL, HD, LL, LL, LL, HD,
            (long)LL*LL, (long)HD*LL, (long)LL*HD, 0, 1.f, 0, 0, 1);

        merge_heads<<<(SS * DD) / 256, 256>>>(av, attn);

        // proj = attn @ wo^T + bo   [2048 x 1024], K=1024
        gemm_tc<<<dim3(SS/GBM, DD/GBN, 1), 256, GEMM_SMEM_BYTES>>>(attn, wo, bo, tmp,
            SS, DD, DD, DD, DD, DD, 0, 0, 0, 0, 1.f, 0, 0, 0);

        add_ln<<<SS, 256>>>(x, tmp, ln1_w + l * DD, ln1_b + l * DD, x);

        // ---- MoE ----
        gate_topk<<<SS, 256>>>(x, gw, gb, topi, topw);
        route_kernel<<<EE, 256>>>(topi, topw, slot, slotw);
        gather_xe<<<EE * CAP, 256>>>(x, slot, xe);

        // h = relu(xe @ w1^T + b1)   batch=8, M=320, N=4096, K=1024
        gemm_tc<<<dim3((CAP+GBM-1)/GBM, FF/GBN, EE), 256, GEMM_SMEM_BYTES>>>(xe, w1l, b1l, hbuf,
            CAP, FF, DD, DD, DD, FF,
            (long)CAP*DD, (long)FF*DD, (long)CAP*FF, FF, 1.f, 1, 0, 0);

        // oe = h @ w2^T + b2   batch=8, M=320, N=1024, K=4096
        gemm_tc<<<dim3((CAP+GBM-1)/GBM, DD/GBN, EE), 256, GEMM_SMEM_BYTES>>>(hbuf, w2l, b2l, oe,
            CAP, DD, FF, FF, FF, DD,
            (long)CAP*FF, (long)DD*FF, (long)CAP*DD, DD, 1.f, 0, 0, 0);

        cudaMemsetAsync(tmp, 0, (size_t)SS * DD * sizeof(float), 0);
        scatter_oe<<<EE * CAP, 256>>>(oe, slot, slotw, tmp);

        add_ln<<<SS, 256>>>(x, tmp, ln2_w + l * DD, ln2_b + l * DD, x);
    }

    // logits = x @ dec_w^T + dec_b   [2048 x 32000], K=1024
    gemm_tc<<<dim3(SS/GBM, (VV+GBN-1)/GBN, 1), 256, GEMM_SMEM_BYTES>>>(x, dec_w, dec_b, out,
        SS, VV, DD, DD, DD, VV, 0, 0, 0, 0, 1.f, 0, 0, 0);
}

// round 12
// speedup vs baseline: 1.5499x; 1.0361x over previous
#include <cuda_runtime.h>
#include <cuda_fp16.h>
#include <math.h>

// ---------------- problem constants ----------------
#define BB 4
#define LL 512
#define VV 32000
#define DD 1024
#define HH 16
#define HD 64
#define NLAYER 2
#define EE 8
#define KK 2
#define FF 4096
#define SS (BB*LL)      // 2048
#define CAP 320
#define D3 (3*DD)       // 3072

typedef __half h16;

// ---------------- static scratch (f32) ----------------
__device__ float g_x[SS*DD];
__device__ float g_qkv[SS*D3];
__device__ float g_sc[BB*HH*LL*LL];     // 64 MB scores
__device__ float g_av[SS*DD];
__device__ float g_tmp[SS*DD];
__device__ float g_oe[EE*CAP*DD];
__device__ int   g_topi[SS*2];
__device__ float g_topw[SS*2];
__device__ int   g_slot[EE*CAP];
__device__ float g_slotw[EE*CAP];

// ---------------- fp16 activation buffers ----------------
__device__ h16 g_xh[SS*DD];
__device__ h16 g_qh[SS*DD];
__device__ h16 g_kh[SS*DD];
__device__ h16 g_kl[SS*DD];
__device__ h16 g_vth[SS*DD];            // V^T per head [bh, d, l]
__device__ h16 g_vtl[SS*DD];
__device__ h16 g_ph[BB*HH*LL*LL];       // probs fp16 (32MB)
__device__ h16 g_attnh[SS*DD];
__device__ h16 g_xeh[EE*CAP*DD];
__device__ h16 g_hh[EE*CAP*FF];

// ---------------- fp16 hi/lo weights (converted once/launch) ----------------
__device__ h16 g_wih[NLAYER*D3*DD];
__device__ h16 g_wil[NLAYER*D3*DD];
__device__ h16 g_woh[NLAYER*DD*DD];
__device__ h16 g_wol[NLAYER*DD*DD];
__device__ h16 g_w1h[NLAYER*EE*FF*DD];
__device__ h16 g_w1l[NLAYER*EE*FF*DD];
__device__ h16 g_w2h[NLAYER*EE*DD*FF];
__device__ h16 g_w2l[NLAYER*EE*DD*FF];
__device__ h16 g_dwh[VV*DD];
__device__ h16 g_dwl[VV*DD];

// ---------------- reductions ----------------
__device__ __forceinline__ float blockReduceSum(float v){
    __shared__ float sh[32];
    int lane = threadIdx.x & 31, wid = threadIdx.x >> 5;
    int nw = (blockDim.x + 31) >> 5;
    #pragma unroll
    for (int o = 16; o > 0; o >>= 1) v += __shfl_down_sync(0xffffffffu, v, o);
    __syncthreads();
    if (lane == 0) sh[wid] = v;
    __syncthreads();
    if (wid == 0) {
        v = (lane < nw) ? sh[lane] : 0.f;
        #pragma unroll
        for (int o = 16; o > 0; o >>= 1) v += __shfl_down_sync(0xffffffffu, v, o);
        if (lane == 0) sh[0] = v;
    }
    __syncthreads();
    return sh[0];
}

__device__ __forceinline__ float blockReduceMax(float v){
    __shared__ float sh[32];
    int lane = threadIdx.x & 31, wid = threadIdx.x >> 5;
    int nw = (blockDim.x + 31) >> 5;
    #pragma unroll
    for (int o = 16; o > 0; o >>= 1) v = fmaxf(v, __shfl_down_sync(0xffffffffu, v, o));
    __syncthreads();
    if (lane == 0) sh[wid] = v;
    __syncthreads();
    if (wid == 0) {
        v = (lane < nw) ? sh[lane] : -1e30f;
        #pragma unroll
        for (int o = 16; o > 0; o >>= 1) v = fmaxf(v, __shfl_down_sync(0xffffffffu, v, o));
        if (lane == 0) sh[0] = v;
    }
    __syncthreads();
    return sh[0];
}

// ---------------- helpers ----------------
#define MMA_F16(d, a, b) \
    asm volatile("mma.sync.aligned.m16n8k16.row.col.f32.f16.f16.f32 " \
        "{%0,%1,%2,%3},{%4,%5,%6,%7},{%8,%9},{%0,%1,%2,%3};" \
        : "+f"(d[0]), "+f"(d[1]), "+f"(d[2]), "+f"(d[3]) \
        : "r"(a[0]), "r"(a[1]), "r"(a[2]), "r"(a[3]), "r"(b[0]), "r"(b[1]))

#define LDSM4(r0, r1, r2, r3, addr) \
    asm volatile("ldmatrix.sync.aligned.m8n8.x4.shared.b16 {%0,%1,%2,%3}, [%4];" \
        : "=r"(r0), "=r"(r1), "=r"(r2), "=r"(r3) : "r"(addr))

__device__ __forceinline__ unsigned h2pack(float x, float y){
    __half2 H; H.x = __float2half_rn(x); H.y = __float2half_rn(y);
    return *(unsigned*)&H;
}
__device__ __forceinline__ void h2splt(float x, float y, unsigned& hi, unsigned& lo){
    __half2 H, L;
    H.x = __float2half_rn(x); H.y = __float2half_rn(y);
    L.x = __float2half_rn(x - __half2float(H.x));
    L.y = __float2half_rn(y - __half2float(H.y));
    hi = *(unsigned*)&H; lo = *(unsigned*)&L;
}
__device__ __forceinline__ void cp16(unsigned dst, const void* src, bool pred){
    asm volatile("cp.async.cg.shared.global [%0], [%1], 16, %2;"
        :: "r"(dst), "l"(src), "r"(pred ? 16 : 0));
}

// ============================================================
// Pure-fp16 tensor-core GEMM (2-pass split):
//   C = act(alpha * A(MxK) * (Bh+Bl)(NxK)^T + bias)
// A single fp16; B fp16 (hi,lo). D = A*Bh + A*Bl.
// Block 128x128x32, 8 warps, warp tile 64x32, m16n8k16.
// 3-stage cp.async pipeline, 1 barrier/iter, no conversion phase.
// Mainloop/warp/iter: 6 cp.async + 16 LDSM + 64 MMA.
// ============================================================
#define GBM 128
#define GBN 128
#define GBK 32
#define LDW 20                            // row stride in 32-bit words
#define TILE_B (GBM * LDW * 4)            // 10240 B per tile
#define STAGE_B (3u * TILE_B)             // A, Bh, Bl = 30720 B
#define NSTAGE 3
#define GEMM_SMEM_BYTES (NSTAGE * STAGE_B)  // 92160 B

__global__ void __launch_bounds__(256, 2)
gemm_h16(const h16* __restrict__ A,
         const h16* __restrict__ Bh, const h16* __restrict__ Bl,
         const float* __restrict__ bias, float* __restrict__ C,
         h16* __restrict__ Chalf,
         int M, int N, int K, int lda, int ldb, int ldc,
         long aStride, long bStride, long cStride, long biasStride,
         float alpha, int relu, int causal, int kcap)
{
    extern __shared__ char smem[];
    int m0 = blockIdx.x * GBM;
    int n0 = blockIdx.y * GBN;
    if (causal && n0 > m0 + GBM - 1) return;             // fully-masked causal block
    if (kcap) { int ke = m0 + GBM; if (ke < K) K = ke; } // zero prob cols past diag

    int z = blockIdx.z;
    A  += (long)z * aStride;
    Bh += (long)z * bStride;  Bl += (long)z * bStride;
    if (C)     C     += (long)z * cStride;
    if (Chalf) Chalf += (long)z * cStride;
    if (bias)  bias  += (long)z * biasStride;

    int tid = threadIdx.x;
    int wid = tid >> 5, lane = tid & 31;
    int wm = (wid & 1) * 64;
    int wn = (wid >> 1) * 32;

    float c[4][4][4];
    #pragma unroll
    for (int i = 0; i < 4; i++)
        #pragma unroll
        for (int j = 0; j < 4; j++)
            #pragma unroll
            for (int r = 0; r < 4; r++) c[i][j][r] = 0.f;

    // cp.async mapping: thread t -> row t>>1, 32B segment (t&1)*32 of the 64B row
    int cpRow = tid >> 1;
    int cpC   = (tid & 1) * 2;       // chunk index 0 or 2 (each chunk = 16B = 8 fp16)
    int gmA = m0 + cpRow;  bool okA = gmA < M;  if (!okA) gmA = 0;
    int gnB = n0 + cpRow;  bool okB = gnB < N;  if (!okB) gnB = 0;

    unsigned sbase = (unsigned)__cvta_generic_to_shared(smem);
    unsigned rowOff = (unsigned)(cpRow * (LDW * 4) + cpC * 16);

    auto issueCp = [&](int kt, int s) {
        unsigned base = sbase + s * STAGE_B;
        const h16* pa  = A  + (long)gmA * lda + kt + cpC * 8;
        const h16* pbh = Bh + (long)gnB * ldb + kt + cpC * 8;
        const h16* pbl = Bl + (long)gnB * ldb + kt + cpC * 8;
        cp16(base + rowOff,                  pa,      okA);
        cp16(base + rowOff + 16,             pa + 8,  okA);
        cp16(base + TILE_B + rowOff,         pbh,     okB);
        cp16(base + TILE_B + rowOff + 16,    pbh + 8, okB);
        cp16(base + 2*TILE_B + rowOff,       pbl,     okB);
        cp16(base + 2*TILE_B + rowOff + 16,  pbl + 8, okB);
        asm volatile("cp.async.commit_group;" ::: "memory");
    };

    // ldmatrix per-thread offsets (words)
    int aoff = (lane & 15) * LDW + ((lane >> 4) << 2);
    int boff = ((lane & 7) + ((lane >> 4) & 1) * 8) * LDW + ((lane >> 3) & 1) * 4;

    int nIter = K / GBK;     // always >= 2 for this model
    issueCp(0, 0);
    issueCp(GBK, 1);

    for (int it = 0; it < nIter; it++) {
        if (it < nIter - 1) asm volatile("cp.async.wait_group 1;" ::: "memory");
        else                asm volatile("cp.async.wait_group 0;" ::: "memory");
        __syncthreads();   // stage it%3 ready; all threads done reading stage (it+2)%3

        int s = it % NSTAGE;
        unsigned sA  = sbase + s * STAGE_B;
        unsigned sBh = sA + TILE_B;
        unsigned sBl = sA + 2 * TILE_B;

        #pragma unroll
        for (int ks = 0; ks < 2; ks++) {
            int kw = ks * 8;
            unsigned ah[4][4], bh[4][2], bl[4][2];
            #pragma unroll
            for (int i = 0; i < 4; i++) {
                unsigned off = ((wm + i * 16) * LDW + aoff + kw) * 4;
                LDSM4(ah[i][0], ah[i][1], ah[i][2], ah[i][3], sA + off);
            }
            #pragma unroll
            for (int p = 0; p < 2; p++) {
                unsigned off = ((wn + p * 16) * LDW + boff + kw) * 4;
                LDSM4(bh[p*2][0], bh[p*2][1], bh[p*2+1][0], bh[p*2+1][1], sBh + off);
                LDSM4(bl[p*2][0], bl[p*2][1], bl[p*2+1][0], bl[p*2+1][1], sBl + off);
            }
            #pragma unroll
            for (int i = 0; i < 4; i++)
                #pragma unroll
                for (int j = 0; j < 4; j++)
                    MMA_F16(c[i][j], ah[i], bh[j]);
            #pragma unroll
            for (int i = 0; i < 4; i++)
                #pragma unroll
                for (int j = 0; j < 4; j++)
                    MMA_F16(c[i][j], ah[i], bl[j]);
        }

        if (it + 2 < nIter) issueCp((it + 2) * GBK, (it + 2) % NSTAGE);
    }

    // ---- epilogue ----
    int cr = lane >> 2, cc = (lane & 3) * 2;
    #pragma unroll
    for (int i = 0; i < 4; i++) {
        #pragma unroll
        for (int j = 0; j < 4; j++) {
            int gn = n0 + wn + j * 8 + cc;
            #pragma unroll
            for (int half = 0; half < 2; half++) {
                int gm = m0 + wm + i * 16 + cr + half * 8;
                if (gm >= M) continue;
                float v0 = c[i][j][half * 2 + 0] * alpha;
                float v1 = c[i][j][half * 2 + 1] * alpha;
                if (bias) {
                    if (gn < N)     v0 += bias[gn];
                    if (gn + 1 < N) v1 += bias[gn + 1];
                }
                if (relu) { v0 = fmaxf(v0, 0.f); v1 = fmaxf(v1, 0.f); }
                if (Chalf) {
                    if (gn + 1 < N)
                        *(unsigned*)(Chalf + (long)gm * ldc + gn) = h2pack(v0, v1);
                } else {
                    if (gn + 1 < N)
                        *(float2*)(C + (long)gm * ldc + gn) = make_float2(v0, v1);
                    else if (gn < N)
                        C[(long)gm * ldc + gn] = v0;
                }
            }
        }
    }
}

// ---------------- weight f32 -> fp16 hi/lo convert ----------------
__global__ void convert_split(const float* __restrict__ src,
                              unsigned* __restrict__ hiw, unsigned* __restrict__ low,
                              long n4)
{
    long i = (long)blockIdx.x * 256 + threadIdx.x;
    if (i >= n4) return;
    float4 v = ((const float4*)src)[i];
    unsigned h0, l0, h1, l1;
    h2splt(v.x, v.y, h0, l0);
    h2splt(v.z, v.w, h1, l1);
    ((uint2*)hiw)[i] = make_uint2(h0, h1);
    ((uint2*)low)[i] = make_uint2(l0, l1);
}

// ---------------- embedding + positional encoding ----------------
__global__ void embed_kernel(const int* __restrict__ src, const float* __restrict__ emb,
                             float* __restrict__ x, h16* __restrict__ xh)
{
    long i = (long)blockIdx.x * 256 + threadIdx.x;
    int s = (int)(i >> 10);
    int d = (int)(i & 1023);
    int l = s & (LL - 1);
    int tok = src[s];
    int half2i = (d >> 1) * 2;
    float div = __expf(-(float)half2i * (logf(10000.f) / (float)DD));
    float arg = (float)l * div;
    float pe = (d & 1) ? cosf(arg) : sinf(arg);
    float v = emb[(long)tok * DD + d] * 32.0f + pe;
    x[i] = v;
    xh[i] = __float2half_rn(v);
}

// ---------------- head split / merge ----------------
__global__ void split_heads(const float* __restrict__ qkv,
                            h16* __restrict__ qh,
                            h16* __restrict__ kh, h16* __restrict__ kl,
                            h16* __restrict__ vth, h16* __restrict__ vtl)
{
    long i = (long)blockIdx.x * 256 + threadIdx.x;
    int s = (int)(i >> 10);
    int dc = (int)(i & 1023);
    int h = dc >> 6;
    int d = dc & 63;
    int b = s >> 9;
    int l = s & 511;
    long srcoff = (long)s * D3 + h * HD + d;
    long dst = (((long)(b * HH + h) * LL) + l) * HD + d;
    qh[dst] = __float2half_rn(qkv[srcoff]);
    float kv = qkv[srcoff + DD];
    h16 khv = __float2half_rn(kv);
    kh[dst] = khv;
    kl[dst] = __float2half_rn(kv - __half2float(khv));
    long vdst = (((long)(b * HH + h) * HD) + d) * LL + l;
    float vv = qkv[srcoff + 2 * DD];
    h16 vhv = __float2half_rn(vv);
    vth[vdst] = vhv;
    vtl[vdst] = __float2half_rn(vv - __half2float(vhv));
}

__global__ void merge_heads(const float* __restrict__ av, h16* __restrict__ oh)
{
    long i = (long)blockIdx.x * 256 + threadIdx.x;
    int s = (int)(i >> 10);
    int dc = (int)(i & 1023);
    int h = dc >> 6;
    int d = dc & 63;
    int b = s >> 9;
    int l = s & 511;
    long srcoff = (((long)(b * HH + h) * LL) + l) * HD + d;
    oh[i] = __float2half_rn(av[srcoff]);
}

// ---------------- causal softmax: f32 scores -> fp16 probs ----------------
__global__ void softmax_causal(const float* __restrict__ sc, h16* __restrict__ ph)
{
    int row = blockIdx.x;
    int q = row & (LL - 1);
    const float* s = sc + (long)row * LL;
    h16* o = ph + (long)row * LL;
    int t = threadIdx.x;

    float mx = -1e30f;
    for (int k = t; k <= q; k += 128) mx = fmaxf(mx, s[k]);
    mx = blockReduceMax(mx);

    float sum = 0.f;
    for (int k = t; k <= q; k += 128) sum += expf(s[k] - mx);
    sum = blockReduceSum(sum);
    float inv = 1.f / sum;
    for (int k = t; k <= q; k += 128)
        o[k] = __float2half_rn(expf(s[k] - mx) * inv);
    h16 z = __float2half(0.f);
    for (int k = q + 1 + t; k < LL; k += 128) o[k] = z;
}

// ---------------- residual + layernorm ----------------
__global__ void add_ln(const float* __restrict__ a, const float* __restrict__ b,
                       const float* __restrict__ w, const float* __restrict__ bb,
                       float* __restrict__ out, h16* __restrict__ oh)
{
    int row = blockIdx.x;
    int t = threadIdx.x;
    const float* pa = a + (long)row * DD;
    const float* pb = b + (long)row * DD;
    float v[4];
    float s = 0.f;
    #pragma unroll
    for (int i = 0; i < 4; i++) {
        int d = t + i * 256;
        v[i] = pa[d] + pb[d];
        s += v[i];
    }
    s = blockReduceSum(s);
    float mean = s * (1.f / DD);
    float qq = 0.f;
    #pragma unroll
    for (int i = 0; i < 4; i++) {
        float dd = v[i] - mean;
        qq += dd * dd;
    }
    qq = blockReduceSum(qq);
    float inv = rsqrtf(qq * (1.f / DD) + 1e-5f);
    #pragma unroll
    for (int i = 0; i < 4; i++) {
        int d = t + i * 256;
        float o = (v[i] - mean) * inv * w[d] + bb[d];
        long idx = (long)row * DD + d;
        out[idx] = o;
        oh[idx] = __float2half_rn(o);
    }
}

// ---------------- MoE gating ----------------
__global__ void gate_topk(const float* __restrict__ x, const float* __restrict__ gw,
                          const float* __restrict__ gb,
                          int* __restrict__ topi, float* __restrict__ topw)
{
    __shared__ float sh[EE * 256];
    int s = blockIdx.x, t = threadIdx.x;
    float p[EE];
    #pragma unroll
    for (int e = 0; e < EE; e++) p[e] = 0.f;
    for (int d = t; d < DD; d += 256) {
        float xv = x[(long)s * DD + d];
        #pragma unroll
        for (int e = 0; e < EE; e++) p[e] += xv * gw[e * DD + d];
    }
    #pragma unroll
    for (int e = 0; e < EE; e++) sh[e * 256 + t] = p[e];
    __syncthreads();
    for (int o = 128; o > 0; o >>= 1) {
        if (t < o) {
            #pragma unroll
            for (int e = 0; e < EE; e++) sh[e * 256 + t] += sh[e * 256 + t + o];
        }
        __syncthreads();
    }
    if (t == 0) {
        float lg[EE];
        float mx = -1e30f;
        #pragma unroll
        for (int e = 0; e < EE; e++) { lg[e] = sh[e * 256] + gb[e]; mx = fmaxf(mx, lg[e]); }
        float sum = 0.f;
        #pragma unroll
        for (int e = 0; e < EE; e++) { lg[e] = expf(lg[e] - mx); sum += lg[e]; }
        float invs = 1.f / sum;
        #pragma unroll
        for (int e = 0; e < EE; e++) lg[e] *= invs;
        int i0 = 0;
        #pragma unroll
        for (int e = 1; e < EE; e++) if (lg[e] > lg[i0]) i0 = e;
        int i1 = (i0 == 0) ? 1 : 0;
        #pragma unroll
        for (int e = 0; e < EE; e++) if (e != i0 && lg[e] > lg[i1]) i1 = e;
        float w0 = lg[i0], w1 = lg[i1];
        float ws = 1.f / (w0 + w1);
        topi[2 * s]     = i0;
        topi[2 * s + 1] = i1;
        topw[2 * s]     = w0 * ws;
        topw[2 * s + 1] = w1 * ws;
    }
}

// ---------------- capacity routing ----------------
__global__ void route_kernel(const int* __restrict__ topi, const float* __restrict__ topw,
                             int* __restrict__ slot, float* __restrict__ slotw)
{
    __shared__ int cnt[256];
    int e = blockIdx.x;
    int t = threadIdx.x;
    int base = t * 8;
    int loc[8]; float lw[8]; int c = 0;
    #pragma unroll
    for (int i = 0; i < 8; i++) {
        int s = base + i;
        float w = -1.f;
        if (topi[2 * s] == e) w = topw[2 * s];
        else if (topi[2 * s + 1] == e) w = topw[2 * s + 1];
        if (w >= 0.f) { loc[c] = s; lw[c] = w; c++; }
    }
    cnt[t] = c;
    __syncthreads();
    for (int off = 1; off < 256; off <<= 1) {
        int v = 0;
        if (t >= off) v = cnt[t - off];
        __syncthreads();
        cnt[t] += v;
        __syncthreads();
    }
    int start = cnt[t] - c;
    for (int i = 0; i < c; i++) {
        int pos = start + i;
        if (pos < CAP) {
            slot[e * CAP + pos]  = loc[i];
            slotw[e * CAP + pos] = lw[i];
        }
    }
    int total = cnt[255];
    __syncthreads();
    for (int p = total + t; p < CAP; p += 256) {
        slot[e * CAP + p]  = -1;
        slotw[e * CAP + p] = 0.f;
    }
}

__global__ void gather_xe(const h16* __restrict__ xh, const int* __restrict__ slot,
                          h16* __restrict__ xeh)
{
    int sl = blockIdx.x;
    int t = slot[sl];
    unsigned* dh = (unsigned*)(xeh + (long)sl * DD);
    if (t < 0) {
        for (int d = threadIdx.x; d < DD / 2; d += 256) dh[d] = 0u;
    } else {
        const unsigned* sh = (const unsigned*)(xh + (long)t * DD);
        for (int d = threadIdx.x; d < DD / 2; d += 256) dh[d] = sh[d];
    }
}

__global__ void scatter_oe(const float* __restrict__ oe, const int* __restrict__ slot,
                           const float* __restrict__ slotw, float* __restrict__ y)
{
    int sl = blockIdx.x;
    int t = slot[sl];
    if (t < 0) return;
    float w = slotw[sl];
    const float* srcp = oe + (long)sl * DD;
    float* dst = y + (long)t * DD;
    for (int d = threadIdx.x; d < DD; d += 256) atomicAdd(&dst[d], srcp[d] * w);
}

// ---------------- host launcher ----------------
extern "C" void kernel_launch(void* const* d_in, const int* in_sizes, int n_in,
                              void* d_out, int out_size)
{
    const int*   src        = (const int*)  d_in[0];
    const float* emb        = (const float*)d_in[1];
    const float* in_proj_w  = (const float*)d_in[2];
    const float* in_proj_b  = (const float*)d_in[3];
    const float* out_proj_w = (const float*)d_in[4];
    const float* out_proj_b = (const float*)d_in[5];
    const float* ln1_w      = (const float*)d_in[6];
    const float* ln1_b      = (const float*)d_in[7];
    const float* ln2_w      = (const float*)d_in[8];
    const float* ln2_b      = (const float*)d_in[9];
    const float* gate_w     = (const float*)d_in[10];
    const float* gate_b     = (const float*)d_in[11];
    const float* w1         = (const float*)d_in[12];
    const float* b1         = (const float*)d_in[13];
    const float* w2         = (const float*)d_in[14];
    const float* b2         = (const float*)d_in[15];
    const float* dec_w      = (const float*)d_in[16];
    const float* dec_b      = (const float*)d_in[17];
    float* out = (float*)d_out;

    static int smem_set = 0;
    if (!smem_set) {
        cudaFuncSetAttribute(gemm_h16, cudaFuncAttributeMaxDynamicSharedMemorySize, GEMM_SMEM_BYTES);
        smem_set = 1;
    }

    float *x, *qkv, *sc, *av, *tmp, *oe, *topw, *slotw;
    int *topi, *slot;
    h16 *xh, *qh, *kh, *kl, *vth, *vtl, *ph, *attnh, *xeh, *hh;
    h16 *wih, *wil, *woh, *wol, *w1h, *w1l, *w2h, *w2l, *dwh, *dwl;

    cudaGetSymbolAddress((void**)&x,    g_x);
    cudaGetSymbolAddress((void**)&qkv,  g_qkv);
    cudaGetSymbolAddress((void**)&sc,   g_sc);
    cudaGetSymbolAddress((void**)&av,   g_av);
    cudaGetSymbolAddress((void**)&tmp,  g_tmp);
    cudaGetSymbolAddress((void**)&oe,   g_oe);
    cudaGetSymbolAddress((void**)&topi, g_topi);
    cudaGetSymbolAddress((void**)&topw, g_topw);
    cudaGetSymbolAddress((void**)&slot, g_slot);
    cudaGetSymbolAddress((void**)&slotw, g_slotw);
    cudaGetSymbolAddress((void**)&xh,   g_xh);
    cudaGetSymbolAddress((void**)&qh,   g_qh);
    cudaGetSymbolAddress((void**)&kh,   g_kh);
    cudaGetSymbolAddress((void**)&kl,   g_kl);
    cudaGetSymbolAddress((void**)&vth,  g_vth);
    cudaGetSymbolAddress((void**)&vtl,  g_vtl);
    cudaGetSymbolAddress((void**)&ph,   g_ph);
    cudaGetSymbolAddress((void**)&attnh, g_attnh);
    cudaGetSymbolAddress((void**)&xeh,  g_xeh);
    cudaGetSymbolAddress((void**)&hh,   g_hh);
    cudaGetSymbolAddress((void**)&wih,  g_wih);
    cudaGetSymbolAddress((void**)&wil,  g_wil);
    cudaGetSymbolAddress((void**)&woh,  g_woh);
    cudaGetSymbolAddress((void**)&wol,  g_wol);
    cudaGetSymbolAddress((void**)&w1h,  g_w1h);
    cudaGetSymbolAddress((void**)&w1l,  g_w1l);
    cudaGetSymbolAddress((void**)&w2h,  g_w2h);
    cudaGetSymbolAddress((void**)&w2l,  g_w2l);
    cudaGetSymbolAddress((void**)&dwh,  g_dwh);
    cudaGetSymbolAddress((void**)&dwl,  g_dwl);

    // ---- weight conversions (once per launch, ~230us total) ----
    auto conv = [&](const float* s, h16* h, h16* l, long n) {
        long n4 = n / 4;
        convert_split<<<(unsigned)((n4 + 255) / 256), 256>>>(s, (unsigned*)h, (unsigned*)l, n4);
    };
    conv(in_proj_w,  wih, wil, (long)NLAYER * D3 * DD);
    conv(out_proj_w, woh, wol, (long)NLAYER * DD * DD);
    conv(w1,         w1h, w1l, (long)NLAYER * EE * FF * DD);
    conv(w2,         w2h, w2l, (long)NLAYER * EE * DD * FF);
    conv(dec_w,      dwh, dwl, (long)VV * DD);

    embed_kernel<<<(SS * DD) / 256, 256>>>(src, emb, x, xh);

    for (int l = 0; l < NLAYER; l++) {
        const float* bi  = in_proj_b  + (long)l * D3;
        const float* bo  = out_proj_b + (long)l * DD;
        const float* gw  = gate_w     + (long)l * EE * DD;
        const float* gb  = gate_b     + (long)l * EE;
        const float* b1l = b1         + (long)l * EE * FF;
        const float* b2l = b2         + (long)l * EE * DD;
        const h16* wihl = wih + (long)l * D3 * DD;
        const h16* will = wil + (long)l * D3 * DD;
        const h16* wohl = woh + (long)l * DD * DD;
        const h16* woll = wol + (long)l * DD * DD;
        const h16* w1hl = w1h + (long)l * EE * FF * DD;
        const h16* w1ll = w1l + (long)l * EE * FF * DD;
        const h16* w2hl = w2h + (long)l * EE * DD * FF;
        const h16* w2ll = w2l + (long)l * EE * DD * FF;

        // qkv = x @ wi^T + bi   [2048 x 3072], K=1024
        gemm_h16<<<dim3(SS/GBM, D3/GBN, 1), 256, GEMM_SMEM_BYTES>>>(
            xh, wihl, will, bi, qkv, nullptr,
            SS, D3, DD, DD, DD, D3, 0, 0, 0, 0, 1.f, 0, 0, 0);

        split_heads<<<(SS * DD) / 256, 256>>>(qkv, qh, kh, kl, vth, vtl);

        // scores = q @ k^T / 8   batch=64, causal block skip
        gemm_h16<<<dim3(LL/GBM, LL/GBN, BB*HH), 256, GEMM_SMEM_BYTES>>>(
            qh, kh, kl, nullptr, sc, nullptr,
            LL, LL, HD, HD, HD, LL,
            (long)LL*HD, (long)LL*HD, (long)LL*LL, 0, 0.125f, 0, 1, 0);

        softmax_causal<<<BB * HH * LL, 128>>>(sc, ph);

        // av = probs @ vt^T   batch=64, K capped by causal zeros
        gemm_h16<<<dim3(LL/GBM, 1, BB*HH), 256, GEMM_SMEM_BYTES>>>(
            ph, vth, vtl, nullptr, av, nullptr,
            LL, HD, LL, LL, LL, HD,
            (long)LL*LL, (long)HD*LL, (long)LL*HD, 0, 1.f, 0, 0, 1);

        merge_heads<<<(SS * DD) / 256, 256>>>(av, attnh);

        // proj = attn @ wo^T + bo
        gemm_h16<<<dim3(SS/GBM, DD/GBN, 1), 256, GEMM_SMEM_BYTES>>>(
            attnh, wohl, woll, bo, tmp, nullptr,
            SS, DD, DD, DD, DD, DD, 0, 0, 0, 0, 1.f, 0, 0, 0);

        add_ln<<<SS, 256>>>(x, tmp, ln1_w + l * DD, ln1_b + l * DD, x, xh);

        // ---- MoE ----
        gate_topk<<<SS, 256>>>(x, gw, gb, topi, topw);
        route_kernel<<<EE, 256>>>(topi, topw, slot, slotw);
        gather_xe<<<EE * CAP, 256>>>(xh, slot, xeh);

        // h = relu(xe @ w1^T + b1) -> fp16 out   [320 x 4096] x8
        gemm_h16<<<dim3((CAP+GBM-1)/GBM, FF/GBN, EE), 256, GEMM_SMEM_BYTES>>>(
            xeh, w1hl, w1ll, b1l, nullptr, hh,
            CAP, FF, DD, DD, DD, FF,
            (long)CAP*DD, (long)FF*DD, (long)CAP*FF, FF, 1.f, 1, 0, 0);

        // oe = h @ w2^T + b2   [320 x 1024] x8, K=4096
        gemm_h16<<<dim3((CAP+GBM-1)/GBM, DD/GBN, EE), 256, GEMM_SMEM_BYTES>>>(
            hh, w2hl, w2ll, b2l, oe, nullptr,
            CAP, DD, FF, FF, FF, DD,
            (long)CAP*FF, (long)DD*FF, (long)CAP*DD, DD, 1.f, 0, 0, 0);

        cudaMemsetAsync(tmp, 0, (size_t)SS * DD * sizeof(float), 0);
        scatter_oe<<<EE * CAP, 256>>>(oe, slot, slotw, tmp);

        add_ln<<<SS, 256>>>(x, tmp, ln2_w + l * DD, ln2_b + l * DD, x, xh);
    }

    // logits = x @ dec_w^T + dec_b   [2048 x 32000], K=1024
    gemm_h16<<<dim3(SS/GBM, VV/GBN, 1), 256, GEMM_SMEM_BYTES>>>(
        xh, dwh, dwl, dec_b, out, nullptr,
        SS, VV, DD, DD, DD, VV, 0, 0, 0, 0, 1.f, 0, 0, 0);
}

// round 13
// speedup vs baseline: 2.1755x; 1.4036x over previous
#include <cuda_runtime.h>
#include <cuda_fp16.h>
#include <math.h>

// ---------------- problem constants ----------------
#define BB 4
#define LL 512
#define VV 32000
#define DD 1024
#define HH 16
#define HD 64
#define NLAYER 2
#define EE 8
#define KK 2
#define FF 4096
#define SS (BB*LL)      // 2048
#define CAP 320
#define D3 (3*DD)       // 3072

typedef __half h16;

// ---------------- static scratch (f32) ----------------
__device__ float g_x[SS*DD];
__device__ float g_qkv[SS*D3];
__device__ float g_sc[BB*HH*LL*LL];     // 64 MB scores
__device__ float g_av[SS*DD];
__device__ float g_tmp[SS*DD];
__device__ float g_oe[EE*CAP*DD];
__device__ int   g_topi[SS*2];
__device__ float g_topw[SS*2];
__device__ int   g_slot[EE*CAP];
__device__ float g_slotw[EE*CAP];

// ---------------- fp16 activation buffers ----------------
__device__ h16 g_xh[SS*DD];
__device__ h16 g_qh[SS*DD];
__device__ h16 g_kh[SS*DD];
__device__ h16 g_vth[SS*DD];            // V^T per head [bh, d, l]
__device__ h16 g_ph[BB*HH*LL*LL];       // probs fp16 (32MB)
__device__ h16 g_attnh[SS*DD];
__device__ h16 g_xeh[EE*CAP*DD];
__device__ h16 g_hh[EE*CAP*FF];

// ---------------- fp16 weights (converted once/launch) ----------------
__device__ h16 g_wih[NLAYER*D3*DD];
__device__ h16 g_woh[NLAYER*DD*DD];
__device__ h16 g_w1h[NLAYER*EE*FF*DD];
__device__ h16 g_w2h[NLAYER*EE*DD*FF];
__device__ h16 g_dwh[VV*DD];

// ---------------- reductions ----------------
__device__ __forceinline__ float blockReduceSum(float v){
    __shared__ float sh[32];
    int lane = threadIdx.x & 31, wid = threadIdx.x >> 5;
    int nw = (blockDim.x + 31) >> 5;
    #pragma unroll
    for (int o = 16; o > 0; o >>= 1) v += __shfl_down_sync(0xffffffffu, v, o);
    __syncthreads();
    if (lane == 0) sh[wid] = v;
    __syncthreads();
    if (wid == 0) {
        v = (lane < nw) ? sh[lane] : 0.f;
        #pragma unroll
        for (int o = 16; o > 0; o >>= 1) v += __shfl_down_sync(0xffffffffu, v, o);
        if (lane == 0) sh[0] = v;
    }
    __syncthreads();
    return sh[0];
}

__device__ __forceinline__ float blockReduceMax(float v){
    __shared__ float sh[32];
    int lane = threadIdx.x & 31, wid = threadIdx.x >> 5;
    int nw = (blockDim.x + 31) >> 5;
    #pragma unroll
    for (int o = 16; o > 0; o >>= 1) v = fmaxf(v, __shfl_down_sync(0xffffffffu, v, o));
    __syncthreads();
    if (lane == 0) sh[wid] = v;
    __syncthreads();
    if (wid == 0) {
        v = (lane < nw) ? sh[lane] : -1e30f;
        #pragma unroll
        for (int o = 16; o > 0; o >>= 1) v = fmaxf(v, __shfl_down_sync(0xffffffffu, v, o));
        if (lane == 0) sh[0] = v;
    }
    __syncthreads();
    return sh[0];
}

// ---------------- helpers ----------------
#define MMA_F16(d, a, b) \
    asm volatile("mma.sync.aligned.m16n8k16.row.col.f32.f16.f16.f32 " \
        "{%0,%1,%2,%3},{%4,%5,%6,%7},{%8,%9},{%0,%1,%2,%3};" \
        : "+f"(d[0]), "+f"(d[1]), "+f"(d[2]), "+f"(d[3]) \
        : "r"(a[0]), "r"(a[1]), "r"(a[2]), "r"(a[3]), "r"(b[0]), "r"(b[1]))

#define LDSM4(r0, r1, r2, r3, addr) \
    asm volatile("ldmatrix.sync.aligned.m8n8.x4.shared.b16 {%0,%1,%2,%3}, [%4];" \
        : "=r"(r0), "=r"(r1), "=r"(r2), "=r"(r3) : "r"(addr))

__device__ __forceinline__ unsigned h2pack(float x, float y){
    __half2 H; H.x = __float2half_rn(x); H.y = __float2half_rn(y);
    return *(unsigned*)&H;
}
__device__ __forceinline__ void cp16(unsigned dst, const void* src, bool pred){
    asm volatile("cp.async.cg.shared.global [%0], [%1], 16, %2;"
        :: "r"(dst), "l"(src), "r"(pred ? 16 : 0));
}

// ============================================================
// Pure-fp16 tensor-core GEMM (single pass):
//   C = act(alpha * A(MxK) * B(NxK)^T + bias)
// A, B single-rounded fp16. Block 128x128x32, 8 warps,
// warp tile 64x32, m16n8k16, 3-stage cp.async, 1 barrier/iter.
// Mainloop/warp/iter: 4 cp.async + 12 LDSM + 32 MMA.
// ============================================================
#define GBM 128
#define GBN 128
#define GBK 32
#define LDW 20                            // row stride in 32-bit words
#define TILE_B (GBM * LDW * 4)            // 10240 B per tile
#define STAGE_B (2u * TILE_B)             // A, B = 20480 B
#define NSTAGE 3
#define GEMM_SMEM_BYTES (NSTAGE * STAGE_B)  // 61440 B

__global__ void __launch_bounds__(256, 2)
gemm_h16(const h16* __restrict__ A, const h16* __restrict__ Bm,
         const float* __restrict__ bias, float* __restrict__ C,
         h16* __restrict__ Chalf,
         int M, int N, int K, int lda, int ldb, int ldc,
         long aStride, long bStride, long cStride, long biasStride,
         float alpha, int relu, int causal, int kcap)
{
    extern __shared__ char smem[];
    int m0 = blockIdx.x * GBM;
    int n0 = blockIdx.y * GBN;
    if (causal && n0 > m0 + GBM - 1) return;             // fully-masked causal block
    if (kcap) { int ke = m0 + GBM; if (ke < K) K = ke; } // zero prob cols past diag

    int z = blockIdx.z;
    A  += (long)z * aStride;
    Bm += (long)z * bStride;
    if (C)     C     += (long)z * cStride;
    if (Chalf) Chalf += (long)z * cStride;
    if (bias)  bias  += (long)z * biasStride;

    int tid = threadIdx.x;
    int wid = tid >> 5, lane = tid & 31;
    int wm = (wid & 1) * 64;
    int wn = (wid >> 1) * 32;

    float c[4][4][4];
    #pragma unroll
    for (int i = 0; i < 4; i++)
        #pragma unroll
        for (int j = 0; j < 4; j++)
            #pragma unroll
            for (int r = 0; r < 4; r++) c[i][j][r] = 0.f;

    // cp.async mapping: thread t -> row t>>1, 32B segment (t&1)*32 of the 64B row
    int cpRow = tid >> 1;
    int cpC   = (tid & 1) * 2;       // chunk index 0 or 2 (each = 16B = 8 fp16)
    int gmA = m0 + cpRow;  bool okA = gmA < M;  if (!okA) gmA = 0;
    int gnB = n0 + cpRow;  bool okB = gnB < N;  if (!okB) gnB = 0;

    unsigned sbase = (unsigned)__cvta_generic_to_shared(smem);
    unsigned rowOff = (unsigned)(cpRow * (LDW * 4) + cpC * 16);

    auto issueCp = [&](int kt, int s) {
        unsigned base = sbase + s * STAGE_B;
        const h16* pa = A  + (long)gmA * lda + kt + cpC * 8;
        const h16* pb = Bm + (long)gnB * ldb + kt + cpC * 8;
        cp16(base + rowOff,               pa,     okA);
        cp16(base + rowOff + 16,          pa + 8, okA);
        cp16(base + TILE_B + rowOff,      pb,     okB);
        cp16(base + TILE_B + rowOff + 16, pb + 8, okB);
        asm volatile("cp.async.commit_group;" ::: "memory");
    };

    // ldmatrix per-thread offsets (words)
    int aoff = (lane & 15) * LDW + ((lane >> 4) << 2);
    int boff = ((lane & 7) + ((lane >> 4) & 1) * 8) * LDW + ((lane >> 3) & 1) * 4;

    int nIter = K / GBK;     // always >= 2 for this model
    issueCp(0, 0);
    issueCp(GBK, 1);

    for (int it = 0; it < nIter; it++) {
        if (it < nIter - 1) asm volatile("cp.async.wait_group 1;" ::: "memory");
        else                asm volatile("cp.async.wait_group 0;" ::: "memory");
        __syncthreads();   // stage it%3 ready; all threads done reading stage (it+2)%3

        int s = it % NSTAGE;
        unsigned sA = sbase + s * STAGE_B;
        unsigned sB = sA + TILE_B;

        #pragma unroll
        for (int ks = 0; ks < 2; ks++) {
            int kw = ks * 8;
            unsigned ah[4][4], bh[4][2];
            #pragma unroll
            for (int i = 0; i < 4; i++) {
                unsigned off = ((wm + i * 16) * LDW + aoff + kw) * 4;
                LDSM4(ah[i][0], ah[i][1], ah[i][2], ah[i][3], sA + off);
            }
            #pragma unroll
            for (int p = 0; p < 2; p++) {
                unsigned off = ((wn + p * 16) * LDW + boff + kw) * 4;
                LDSM4(bh[p*2][0], bh[p*2][1], bh[p*2+1][0], bh[p*2+1][1], sB + off);
            }
            #pragma unroll
            for (int i = 0; i < 4; i++)
                #pragma unroll
                for (int j = 0; j < 4; j++)
                    MMA_F16(c[i][j], ah[i], bh[j]);
        }

        if (it + 2 < nIter) issueCp((it + 2) * GBK, (it + 2) % NSTAGE);
    }

    // ---- epilogue ----
    int cr = lane >> 2, cc = (lane & 3) * 2;
    #pragma unroll
    for (int i = 0; i < 4; i++) {
        #pragma unroll
        for (int j = 0; j < 4; j++) {
            int gn = n0 + wn + j * 8 + cc;
            #pragma unroll
            for (int half = 0; half < 2; half++) {
                int gm = m0 + wm + i * 16 + cr + half * 8;
                if (gm >= M) continue;
                float v0 = c[i][j][half * 2 + 0] * alpha;
                float v1 = c[i][j][half * 2 + 1] * alpha;
                if (bias) {
                    if (gn < N)     v0 += bias[gn];
                    if (gn + 1 < N) v1 += bias[gn + 1];
                }
                if (relu) { v0 = fmaxf(v0, 0.f); v1 = fmaxf(v1, 0.f); }
                if (Chalf) {
                    if (gn + 1 < N)
                        *(unsigned*)(Chalf + (long)gm * ldc + gn) = h2pack(v0, v1);
                } else {
                    if (gn + 1 < N)
                        *(float2*)(C + (long)gm * ldc + gn) = make_float2(v0, v1);
                    else if (gn < N)
                        C[(long)gm * ldc + gn] = v0;
                }
            }
        }
    }
}

// ---------------- weight f32 -> fp16 convert ----------------
__global__ void convert_h(const float* __restrict__ src,
                          unsigned* __restrict__ hiw, long n4)
{
    long i = (long)blockIdx.x * 256 + threadIdx.x;
    if (i >= n4) return;
    float4 v = ((const float4*)src)[i];
    ((uint2*)hiw)[i] = make_uint2(h2pack(v.x, v.y), h2pack(v.z, v.w));
}

// ---------------- embedding + positional encoding ----------------
__global__ void embed_kernel(const int* __restrict__ src, const float* __restrict__ emb,
                             float* __restrict__ x, h16* __restrict__ xh)
{
    long i = (long)blockIdx.x * 256 + threadIdx.x;
    int s = (int)(i >> 10);
    int d = (int)(i & 1023);
    int l = s & (LL - 1);
    int tok = src[s];
    int half2i = (d >> 1) * 2;
    float div = __expf(-(float)half2i * (logf(10000.f) / (float)DD));
    float arg = (float)l * div;
    float pe = (d & 1) ? cosf(arg) : sinf(arg);
    float v = emb[(long)tok * DD + d] * 32.0f + pe;
    x[i] = v;
    xh[i] = __float2half_rn(v);
}

// ---------------- head split / merge ----------------
__global__ void split_heads(const float* __restrict__ qkv,
                            h16* __restrict__ qh, h16* __restrict__ kh,
                            h16* __restrict__ vth)
{
    long i = (long)blockIdx.x * 256 + threadIdx.x;
    int s = (int)(i >> 10);
    int dc = (int)(i & 1023);
    int h = dc >> 6;
    int d = dc & 63;
    int b = s >> 9;
    int l = s & 511;
    long srcoff = (long)s * D3 + h * HD + d;
    long dst = (((long)(b * HH + h) * LL) + l) * HD + d;
    qh[dst] = __float2half_rn(qkv[srcoff]);
    kh[dst] = __float2half_rn(qkv[srcoff + DD]);
    long vdst = (((long)(b * HH + h) * HD) + d) * LL + l;
    vth[vdst] = __float2half_rn(qkv[srcoff + 2 * DD]);
}

__global__ void merge_heads(const float* __restrict__ av, h16* __restrict__ oh)
{
    long i = (long)blockIdx.x * 256 + threadIdx.x;
    int s = (int)(i >> 10);
    int dc = (int)(i & 1023);
    int h = dc >> 6;
    int d = dc & 63;
    int b = s >> 9;
    int l = s & 511;
    long srcoff = (((long)(b * HH + h) * LL) + l) * HD + d;
    oh[i] = __float2half_rn(av[srcoff]);
}

// ---------------- causal softmax: f32 scores -> fp16 probs ----------------
__global__ void softmax_causal(const float* __restrict__ sc, h16* __restrict__ ph)
{
    int row = blockIdx.x;
    int q = row & (LL - 1);
    const float* s = sc + (long)row * LL;
    h16* o = ph + (long)row * LL;
    int t = threadIdx.x;

    float mx = -1e30f;
    for (int k = t; k <= q; k += 128) mx = fmaxf(mx, s[k]);
    mx = blockReduceMax(mx);

    float sum = 0.f;
    for (int k = t; k <= q; k += 128) sum += expf(s[k] - mx);
    sum = blockReduceSum(sum);
    float inv = 1.f / sum;
    for (int k = t; k <= q; k += 128)
        o[k] = __float2half_rn(expf(s[k] - mx) * inv);
    h16 z = __float2half(0.f);
    for (int k = q + 1 + t; k < LL; k += 128) o[k] = z;
}

// ---------------- residual + layernorm ----------------
__global__ void add_ln(const float* __restrict__ a, const float* __restrict__ b,
                       const float* __restrict__ w, const float* __restrict__ bb,
                       float* __restrict__ out, h16* __restrict__ oh)
{
    int row = blockIdx.x;
    int t = threadIdx.x;
    const float* pa = a + (long)row * DD;
    const float* pb = b + (long)row * DD;
    float v[4];
    float s = 0.f;
    #pragma unroll
    for (int i = 0; i < 4; i++) {
        int d = t + i * 256;
        v[i] = pa[d] + pb[d];
        s += v[i];
    }
    s = blockReduceSum(s);
    float mean = s * (1.f / DD);
    float qq = 0.f;
    #pragma unroll
    for (int i = 0; i < 4; i++) {
        float dd = v[i] - mean;
        qq += dd * dd;
    }
    qq = blockReduceSum(qq);
    float inv = rsqrtf(qq * (1.f / DD) + 1e-5f);
    #pragma unroll
    for (int i = 0; i < 4; i++) {
        int d = t + i * 256;
        float o = (v[i] - mean) * inv * w[d] + bb[d];
        long idx = (long)row * DD + d;
        out[idx] = o;
        oh[idx] = __float2half_rn(o);
    }
}

// ---------------- MoE gating ----------------
__global__ void gate_topk(const float* __restrict__ x, const float* __restrict__ gw,
                          const float* __restrict__ gb,
                          int* __restrict__ topi, float* __restrict__ topw)
{
    __shared__ float sh[EE * 256];
    int s = blockIdx.x, t = threadIdx.x;
    float p[EE];
    #pragma unroll
    for (int e = 0; e < EE; e++) p[e] = 0.f;
    for (int d = t; d < DD; d += 256) {
        float xv = x[(long)s * DD + d];
        #pragma unroll
        for (int e = 0; e < EE; e++) p[e] += xv * gw[e * DD + d];
    }
    #pragma unroll
    for (int e = 0; e < EE; e++) sh[e * 256 + t] = p[e];
    __syncthreads();
    for (int o = 128; o > 0; o >>= 1) {
        if (t < o) {
            #pragma unroll
            for (int e = 0; e < EE; e++) sh[e * 256 + t] += sh[e * 256 + t + o];
        }
        __syncthreads();
    }
    if (t == 0) {
        float lg[EE];
        float mx = -1e30f;
        #pragma unroll
        for (int e = 0; e < EE; e++) { lg[e] = sh[e * 256] + gb[e]; mx = fmaxf(mx, lg[e]); }
        float sum = 0.f;
        #pragma unroll
        for (int e = 0; e < EE; e++) { lg[e] = expf(lg[e] - mx); sum += lg[e]; }
        float invs = 1.f / sum;
        #pragma unroll
        for (int e = 0; e < EE; e++) lg[e] *= invs;
        int i0 = 0;
        #pragma unroll
        for (int e = 1; e < EE; e++) if (lg[e] > lg[i0]) i0 = e;
        int i1 = (i0 == 0) ? 1 : 0;
        #pragma unroll
        for (int e = 0; e < EE; e++) if (e != i0 && lg[e] > lg[i1]) i1 = e;
        float w0 = lg[i0], w1 = lg[i1];
        float ws = 1.f / (w0 + w1);
        topi[2 * s]     = i0;
        topi[2 * s + 1] = i1;
        topw[2 * s]     = w0 * ws;
        topw[2 * s + 1] = w1 * ws;
    }
}

// ---------------- capacity routing ----------------
__global__ void route_kernel(const int* __restrict__ topi, const float* __restrict__ topw,
                             int* __restrict__ slot, float* __restrict__ slotw)
{
    __shared__ int cnt[256];
    int e = blockIdx.x;
    int t = threadIdx.x;
    int base = t * 8;
    int loc[8]; float lw[8]; int c = 0;
    #pragma unroll
    for (int i = 0; i < 8; i++) {
        int s = base + i;
        float w = -1.f;
        if (topi[2 * s] == e) w = topw[2 * s];
        else if (topi[2 * s + 1] == e) w = topw[2 * s + 1];
        if (w >= 0.f) { loc[c] = s; lw[c] = w; c++; }
    }
    cnt[t] = c;
    __syncthreads();
    for (int off = 1; off < 256; off <<= 1) {
        int v = 0;
        if (t >= off) v = cnt[t - off];
        __syncthreads();
        cnt[t] += v;
        __syncthreads();
    }
    int start = cnt[t] - c;
    for (int i = 0; i < c; i++) {
        int pos = start + i;
        if (pos < CAP) {
            slot[e * CAP + pos]  = loc[i];
            slotw[e * CAP + pos] = lw[i];
        }
    }
    int total = cnt[255];
    __syncthreads();
    for (int p = total + t; p < CAP; p += 256) {
        slot[e * CAP + p]  = -1;
        slotw[e * CAP + p] = 0.f;
    }
}

__global__ void gather_xe(const h16* __restrict__ xh, const int* __restrict__ slot,
                          h16* __restrict__ xeh)
{
    int sl = blockIdx.x;
    int t = slot[sl];
    unsigned* dh = (unsigned*)(xeh + (long)sl * DD);
    if (t < 0) {
        for (int d = threadIdx.x; d < DD / 2; d += 256) dh[d] = 0u;
    } else {
        const unsigned* sh = (const unsigned*)(xh + (long)t * DD);
        for (int d = threadIdx.x; d < DD / 2; d += 256) dh[d] = sh[d];
    }
}

__global__ void scatter_oe(const float* __restrict__ oe, const int* __restrict__ slot,
                           const float* __restrict__ slotw, float* __restrict__ y)
{
    int sl = blockIdx.x;
    int t = slot[sl];
    if (t < 0) return;
    float w = slotw[sl];
    const float* srcp = oe + (long)sl * DD;
    float* dst = y + (long)t * DD;
    for (int d = threadIdx.x; d < DD; d += 256) atomicAdd(&dst[d], srcp[d] * w);
}

// ---------------- host launcher ----------------
extern "C" void kernel_launch(void* const* d_in, const int* in_sizes, int n_in,
                              void* d_out, int out_size)
{
    const int*   src        = (const int*)  d_in[0];
    const float* emb        = (const float*)d_in[1];
    const float* in_proj_w  = (const float*)d_in[2];
    const float* in_proj_b  = (const float*)d_in[3];
    const float* out_proj_w = (const float*)d_in[4];
    const float* out_proj_b = (const float*)d_in[5];
    const float* ln1_w      = (const float*)d_in[6];
    const float* ln1_b      = (const float*)d_in[7];
    const float* ln2_w      = (const float*)d_in[8];
    const float* ln2_b      = (const float*)d_in[9];
    const float* gate_w     = (const float*)d_in[10];
    const float* gate_b     = (const float*)d_in[11];
    const float* w1         = (const float*)d_in[12];
    const float* b1         = (const float*)d_in[13];
    const float* w2         = (const float*)d_in[14];
    const float* b2         = (const float*)d_in[15];
    const float* dec_w      = (const float*)d_in[16];
    const float* dec_b      = (const float*)d_in[17];
    float* out = (float*)d_out;

    static int smem_set = 0;
    if (!smem_set) {
        cudaFuncSetAttribute(gemm_h16, cudaFuncAttributeMaxDynamicSharedMemorySize, GEMM_SMEM_BYTES);
        smem_set = 1;
    }

    float *x, *qkv, *sc, *av, *tmp, *oe, *topw, *slotw;
    int *topi, *slot;
    h16 *xh, *qh, *kh, *vth, *ph, *attnh, *xeh, *hh;
    h16 *wih, *woh, *w1h, *w2h, *dwh;

    cudaGetSymbolAddress((void**)&x,    g_x);
    cudaGetSymbolAddress((void**)&qkv,  g_qkv);
    cudaGetSymbolAddress((void**)&sc,   g_sc);
    cudaGetSymbolAddress((void**)&av,   g_av);
    cudaGetSymbolAddress((void**)&tmp,  g_tmp);
    cudaGetSymbolAddress((void**)&oe,   g_oe);
    cudaGetSymbolAddress((void**)&topi, g_topi);
    cudaGetSymbolAddress((void**)&topw, g_topw);
    cudaGetSymbolAddress((void**)&slot, g_slot);
    cudaGetSymbolAddress((void**)&slotw, g_slotw);
    cudaGetSymbolAddress((void**)&xh,   g_xh);
    cudaGetSymbolAddress((void**)&qh,   g_qh);
    cudaGetSymbolAddress((void**)&kh,   g_kh);
    cudaGetSymbolAddress((void**)&vth,  g_vth);
    cudaGetSymbolAddress((void**)&ph,   g_ph);
    cudaGetSymbolAddress((void**)&attnh, g_attnh);
    cudaGetSymbolAddress((void**)&xeh,  g_xeh);
    cudaGetSymbolAddress((void**)&hh,   g_hh);
    cudaGetSymbolAddress((void**)&wih,  g_wih);
    cudaGetSymbolAddress((void**)&woh,  g_woh);
    cudaGetSymbolAddress((void**)&w1h,  g_w1h);
    cudaGetSymbolAddress((void**)&w2h,  g_w2h);
    cudaGetSymbolAddress((void**)&dwh,  g_dwh);

    // ---- weight conversions (once per launch, ~170us total) ----
    auto conv = [&](const float* s, h16* h, long n) {
        long n4 = n / 4;
        convert_h<<<(unsigned)((n4 + 255) / 256), 256>>>(s, (unsigned*)h, n4);
    };
    conv(in_proj_w,  wih, (long)NLAYER * D3 * DD);
    conv(out_proj_w, woh, (long)NLAYER * DD * DD);
    conv(w1,         w1h, (long)NLAYER * EE * FF * DD);
    conv(w2,         w2h, (long)NLAYER * EE * DD * FF);
    conv(dec_w,      dwh, (long)VV * DD);

    embed_kernel<<<(SS * DD) / 256, 256>>>(src, emb, x, xh);

    for (int l = 0; l < NLAYER; l++) {
        const float* bi  = in_proj_b  + (long)l * D3;
        const float* bo  = out_proj_b + (long)l * DD;
        const float* gw  = gate_w     + (long)l * EE * DD;
        const float* gb  = gate_b     + (long)l * EE;
        const float* b1l = b1         + (long)l * EE * FF;
        const float* b2l = b2         + (long)l * EE * DD;
        const h16* wihl = wih + (long)l * D3 * DD;
        const h16* wohl = woh + (long)l * DD * DD;
        const h16* w1hl = w1h + (long)l * EE * FF * DD;
        const h16* w2hl = w2h + (long)l * EE * DD * FF;

        // qkv = x @ wi^T + bi   [2048 x 3072], K=1024
        gemm_h16<<<dim3(SS/GBM, D3/GBN, 1), 256, GEMM_SMEM_BYTES>>>(
            xh, wihl, bi, qkv, nullptr,
            SS, D3, DD, DD, DD, D3, 0, 0, 0, 0, 1.f, 0, 0, 0);

        split_heads<<<(SS * DD) / 256, 256>>>(qkv, qh, kh, vth);

        // scores = q @ k^T / 8   batch=64, causal block skip
        gemm_h16<<<dim3(LL/GBM, LL/GBN, BB*HH), 256, GEMM_SMEM_BYTES>>>(
            qh, kh, nullptr, sc, nullptr,
            LL, LL, HD, HD, HD, LL,
            (long)LL*HD, (long)LL*HD, (long)LL*LL, 0, 0.125f, 0, 1, 0);

        softmax_causal<<<BB * HH * LL, 128>>>(sc, ph);

        // av = probs @ vt^T   batch=64, K capped by causal zeros
        gemm_h16<<<dim3(LL/GBM, 1, BB*HH), 256, GEMM_SMEM_BYTES>>>(
            ph, vth, nullptr, av, nullptr,
            LL, HD, LL, LL, LL, HD,
            (long)LL*LL, (long)HD*LL, (long)LL*HD, 0, 1.f, 0, 0, 1);

        merge_heads<<<(SS * DD) / 256, 256>>>(av, attnh);

        // proj = attn @ wo^T + bo
        gemm_h16<<<dim3(SS/GBM, DD/GBN, 1), 256, GEMM_SMEM_BYTES>>>(
            attnh, wohl, bo, tmp, nullptr,
            SS, DD, DD, DD, DD, DD, 0, 0, 0, 0, 1.f, 0, 0, 0);

        add_ln<<<SS, 256>>>(x, tmp, ln1_w + l * DD, ln1_b + l * DD, x, xh);

        // ---- MoE ----
        gate_topk<<<SS, 256>>>(x, gw, gb, topi, topw);
        route_kernel<<<EE, 256>>>(topi, topw, slot, slotw);
        gather_xe<<<EE * CAP, 256>>>(xh, slot, xeh);

        // h = relu(xe @ w1^T + b1) -> fp16 out   [320 x 4096] x8
        gemm_h16<<<dim3((CAP+GBM-1)/GBM, FF/GBN, EE), 256, GEMM_SMEM_BYTES>>>(
            xeh, w1hl, b1l, nullptr, hh,
            CAP, FF, DD, DD, DD, FF,
            (long)CAP*DD, (long)FF*DD, (long)CAP*FF, FF, 1.f, 1, 0, 0);

        // oe = h @ w2^T + b2   [320 x 1024] x8, K=4096
        gemm_h16<<<dim3((CAP+GBM-1)/GBM, DD/GBN, EE), 256, GEMM_SMEM_BYTES>>>(
            hh, w2hl, b2l, oe, nullptr,
            CAP, DD, FF, FF, FF, DD,
            (long)CAP*FF, (long)DD*FF, (long)CAP*DD, DD, 1.f, 0, 0, 0);

        cudaMemsetAsync(tmp, 0, (size_t)SS * DD * sizeof(float), 0);
        scatter_oe<<<EE * CAP, 256>>>(oe, slot, slotw, tmp);

        add_ln<<<SS, 256>>>(x, tmp, ln2_w + l * DD, ln2_b + l * DD, x, xh);
    }

    // logits = x @ dec_w^T + dec_b   [2048 x 32000], K=1024
    gemm_h16<<<dim3(SS/GBM, VV/GBN, 1), 256, GEMM_SMEM_BYTES>>>(
        xh, dwh, dec_b, out, nullptr,
        SS, VV, DD, DD, DD, VV, 0, 0, 0, 0, 1.f, 0, 0, 0);
}